// round 7
// baseline (speedup 1.0000x reference)
#include <cuda_runtime.h>

#define HH 128
#define WW 128
#define HWN 16384
#define BHW (4 * 16384)
#define BN 4
#define CN 64

typedef unsigned long long ull;

__device__ __constant__ int c_RATES[4] = {2, 3, 5, 9};

// Scratch (static device globals: allocation-free, graph-capturable)
__device__ float g_xhwc[BN * HWN * CN];            // [b][p][c]
__device__ float g_off[4 * 18 * BHW];              // [j][k2][b*HW+p]  planar
__device__ float g_dwt[4 * 9 * 64 * 64];           // [i][k][c][o]
__device__ float g_cat[4 * BN * CN * HWN];         // [i][b][o][p]
__device__ float g_bsums[4 * BN * 128 * 64];       // [i][b][row][o]
__device__ float g_gate[BN * 256];                 // 1 + sigmoid(...)

__device__ __forceinline__ ull pack2(float a, float b) {
    ull r;
    asm("mov.b64 %0, {%1, %2};" : "=l"(r) : "f"(a), "f"(b));
    return r;
}
__device__ __forceinline__ void ffma2(ull& d, ull a, ull b) {
    asm("fma.rn.f32x2 %0, %1, %2, %0;" : "+l"(d) : "l"(a), "l"(b));
}
__device__ __forceinline__ void bar_sync(int id) {
    asm volatile("bar.sync %0, 256;" :: "r"(id) : "memory");
}
__device__ __forceinline__ void bar_arrive(int id) {
    asm volatile("bar.arrive %0, 256;" :: "r"(id) : "memory");
}

// ---------------- K1: NCHW -> NHWC transpose of x ----------------
__global__ void transpose_kernel(const float* __restrict__ x) {
    __shared__ float tile[32][33];
    int b  = blockIdx.z;
    int p0 = blockIdx.x * 32;
    int c0 = blockIdx.y * 32;
    for (int i = threadIdx.y; i < 32; i += 8)
        tile[i][threadIdx.x] = x[(b * 64 + c0 + i) * HWN + p0 + threadIdx.x];
    __syncthreads();
    for (int i = threadIdx.y; i < 32; i += 8)
        g_xhwc[(b * HWN + p0 + i) * 64 + c0 + threadIdx.x] = tile[threadIdx.x][i];
}

// ---------------- K1b: dw (i,o,c,3,3) -> g_dwt [i][k][c][o] ----------------
__global__ void dwt_kernel(const float* __restrict__ dw) {
    int idx = blockIdx.x * 256 + threadIdx.x;  // < 147456
    int i  = idx / 36864;
    int r  = idx % 36864;
    int k  = r / 4096;
    int r2 = r & 4095;
    int c  = r2 >> 6;
    int o  = r2 & 63;
    g_dwt[idx] = dw[((i * 64 + o) * 64 + c) * 9 + k];
}

// ---------------- K2: offset conv (64 -> 18, dilated 3x3, relu), f32x2 ----------------
// writes PLANAR layout: g_off[(j*18+k2)*BHW + b*HWN + p]
__global__ __launch_bounds__(256) void offset_kernel(const float* __restrict__ x,
                                                     const float* __restrict__ ow,
                                                     const float* __restrict__ ob) {
    __shared__ float ow_sh[9 * 64 * 20];
    int j = blockIdx.z, b = blockIdx.y;
    int rate = c_RATES[j];
    int tid = threadIdx.x;
    for (int idx = tid; idx < 9 * 64 * 20; idx += 256) {
        int k2 = idx % 20;
        int rest = idx / 20;
        int c = rest % 64;
        int t = rest / 64;
        ow_sh[idx] = (k2 < 18) ? ow[((j * 18 + k2) * 64 + c) * 9 + t] : 0.f;
    }
    __syncthreads();

    int p = blockIdx.x * 256 + tid;
    int y = p >> 7, xx = p & 127;
    ull acc2[10];
#pragma unroll
    for (int q = 0; q < 9; q++) acc2[q] = pack2(ob[j * 18 + 2 * q], ob[j * 18 + 2 * q + 1]);
    acc2[9] = 0ull;

    const float* xb = x + b * 64 * HWN;
    for (int t = 0; t < 9; t++) {
        int tyv = y + (t / 3 - 1) * rate;
        int txv = xx + (t % 3 - 1) * rate;
        if ((unsigned)tyv >= HH || (unsigned)txv >= WW) continue;
        const float* xp = xb + tyv * WW + txv;
#pragma unroll 4
        for (int c = 0; c < 64; c++) {
            float xc = xp[c * HWN];  // coalesced across warp
            ull xcc = pack2(xc, xc);
            const ull* wr = (const ull*)&ow_sh[(t * 64 + c) * 20];  // broadcast
#pragma unroll
            for (int q = 0; q < 10; q++) ffma2(acc2[q], wr[q], xcc);
        }
    }
    float* og = g_off + j * 18 * BHW + b * HWN + p;  // plane stride BHW, coalesced
#pragma unroll
    for (int q = 0; q < 9; q++) {
        float2 v = *(float2*)&acc2[q];
        og[(2 * q) * BHW]     = fmaxf(v.x, 0.f);
        og[(2 * q + 1) * BHW] = fmaxf(v.y, 0.f);
    }
}

// ---------------- K3: warp-specialized deform sample + GEMM per branch ----------------
// 256 threads: warps 0-3 = producers (gather), warps 4-7 = consumers (GEMM)
// S double-buffered; named barriers FULL=1+buf, EMPTY=3+buf (count 256)
// S swizzle: phys(sp, c) = (sp + 4*(c>>2)) & 127
#define SPITCH 132
__global__ __launch_bounds__(256, 2) void branch_kernel() {
    extern __shared__ float smem[];
    // S0 = smem, S1 = smem + 8448

    int i = blockIdx.z, b = blockIdx.y, row = blockIdx.x;
    int p0 = row * 128;
    int j = (i + 3) & 3;
    int rate = c_RATES[i];
    int tid = threadIdx.x;
    int warp = tid >> 5;

    const float* xb   = &g_xhwc[b * HWN * 64];
    const float* dwt  = &g_dwt[i * 9 * 4096];
    const float* offb = g_off + j * 18 * BHW + b * HWN + p0;

    if (warp < 4) {
        // ================= PRODUCER =================
        int lane8 = tid & 7;
        int pxi   = (tid >> 3) & 3;
        int ca  = lane8 * 4;
        int sha = 4 * lane8;
        int shb = 4 * lane8 + 32;

        for (int k = 0; k < 9; k++) {
            int buf = k & 1;
            if (k >= 2) bar_sync(3 + buf);       // wait consumers done with this buffer
            float* S_sh = smem + buf * 8448;

            int kyr = (k / 3 - 1) * rate;
            int kxr = (k % 3 - 1) * rate;
            const float* offY = offb + (2 * k) * BHW;
            const float* offX = offb + (2 * k + 1) * BHW;
#pragma unroll 2
            for (int g = 0; g < 8; g++) {
                int sp = warp * 32 + g * 4 + pxi;
                float dy = __ldg(offY + sp);
                float dx = __ldg(offX + sp);
                float py = (float)(row + kyr) + dy;
                float px = (float)(sp + kxr) + dx;
                float fy = floorf(py), fx = floorf(px);
                int iy0 = (int)fy, ix0 = (int)fx;
                float wy1 = py - fy, wx1 = px - fx;
                float wy0 = 1.f - wy1, wx0 = 1.f - wx1;
                bool vy0 = (unsigned)iy0 < HH, vy1 = (unsigned)(iy0 + 1) < HH;
                bool vx0 = (unsigned)ix0 < WW, vx1 = (unsigned)(ix0 + 1) < WW;
                float w00 = (vy0 && vx0) ? wy0 * wx0 : 0.f;
                float w01 = (vy0 && vx1) ? wy0 * wx1 : 0.f;
                float w10 = (vy1 && vx0) ? wy1 * wx0 : 0.f;
                float w11 = (vy1 && vx1) ? wy1 * wx1 : 0.f;
                ull w00d = pack2(w00, w00), w01d = pack2(w01, w01);
                ull w10d = pack2(w10, w10), w11d = pack2(w11, w11);
                int cy0 = min(max(iy0, 0), HH - 1), cy1 = min(max(iy0 + 1, 0), HH - 1);
                int cx0 = min(max(ix0, 0), WW - 1), cx1 = min(max(ix0 + 1, 0), WW - 1);
                const float* b00 = xb + (cy0 * WW + cx0) * 64;
                const float* b01 = xb + (cy0 * WW + cx1) * 64;
                const float* b10 = xb + (cy1 * WW + cx0) * 64;
                const float* b11 = xb + (cy1 * WW + cx1) * 64;
                {
                    ulonglong2 t00 = *(const ulonglong2*)(b00 + ca);
                    ulonglong2 t01 = *(const ulonglong2*)(b01 + ca);
                    ulonglong2 t10 = *(const ulonglong2*)(b10 + ca);
                    ulonglong2 t11 = *(const ulonglong2*)(b11 + ca);
                    ull r0 = 0, r1 = 0;
                    ffma2(r0, w00d, t00.x); ffma2(r1, w00d, t00.y);
                    ffma2(r0, w01d, t01.x); ffma2(r1, w01d, t01.y);
                    ffma2(r0, w10d, t10.x); ffma2(r1, w10d, t10.y);
                    ffma2(r0, w11d, t11.x); ffma2(r1, w11d, t11.y);
                    float2 f0 = *(float2*)&r0, f1 = *(float2*)&r1;
                    int pa = (sp + sha) & 127;
                    float* d = &S_sh[ca * SPITCH + pa];
                    d[0]          = f0.x;
                    d[SPITCH]     = f0.y;
                    d[2 * SPITCH] = f1.x;
                    d[3 * SPITCH] = f1.y;
                }
                {
                    ulonglong2 t00 = *(const ulonglong2*)(b00 + ca + 32);
                    ulonglong2 t01 = *(const ulonglong2*)(b01 + ca + 32);
                    ulonglong2 t10 = *(const ulonglong2*)(b10 + ca + 32);
                    ulonglong2 t11 = *(const ulonglong2*)(b11 + ca + 32);
                    ull r0 = 0, r1 = 0;
                    ffma2(r0, w00d, t00.x); ffma2(r1, w00d, t00.y);
                    ffma2(r0, w01d, t01.x); ffma2(r1, w01d, t01.y);
                    ffma2(r0, w10d, t10.x); ffma2(r1, w10d, t10.y);
                    ffma2(r0, w11d, t11.x); ffma2(r1, w11d, t11.y);
                    float2 f0 = *(float2*)&r0, f1 = *(float2*)&r1;
                    int pb = (sp + shb) & 127;
                    float* d = &S_sh[(ca + 32) * SPITCH + pb];
                    d[0]          = f0.x;
                    d[SPITCH]     = f0.y;
                    d[2 * SPITCH] = f1.x;
                    d[3 * SPITCH] = f1.y;
                }
            }
            bar_arrive(1 + buf);                 // signal buffer full
        }
    } else {
        // ================= CONSUMER =================
        int ctid = tid - 128;        // 0..127
        int tx = ctid & 15, ty = ctid >> 4;

        ull acc[8][4];
#pragma unroll
        for (int oy = 0; oy < 8; oy++)
#pragma unroll
            for (int q = 0; q < 4; q++) acc[oy][q] = 0ull;

        for (int k = 0; k < 9; k++) {
            int buf = k & 1;
            bar_sync(1 + buf);                   // wait buffer full
            const float* S_sh = smem + buf * 8448;
            const float* Ak = dwt + k * 4096;
#pragma unroll 4
            for (int c = 0; c < 64; c++) {
                float4 a0 = __ldg((const float4*)(Ak + c * 64 + ty * 8));
                float4 a1 = __ldg((const float4*)(Ak + c * 64 + ty * 8 + 4));
                int sh = c & ~3;
                ulonglong2 B0 = *(const ulonglong2*)&S_sh[c * SPITCH + ((tx * 4 + sh) & 127)];
                ulonglong2 B1 = *(const ulonglong2*)&S_sh[c * SPITCH + ((tx * 4 + 64 + sh) & 127)];
                ull aa;
                aa = pack2(a0.x, a0.x); ffma2(acc[0][0], aa, B0.x); ffma2(acc[0][1], aa, B0.y); ffma2(acc[0][2], aa, B1.x); ffma2(acc[0][3], aa, B1.y);
                aa = pack2(a0.y, a0.y); ffma2(acc[1][0], aa, B0.x); ffma2(acc[1][1], aa, B0.y); ffma2(acc[1][2], aa, B1.x); ffma2(acc[1][3], aa, B1.y);
                aa = pack2(a0.z, a0.z); ffma2(acc[2][0], aa, B0.x); ffma2(acc[2][1], aa, B0.y); ffma2(acc[2][2], aa, B1.x); ffma2(acc[2][3], aa, B1.y);
                aa = pack2(a0.w, a0.w); ffma2(acc[3][0], aa, B0.x); ffma2(acc[3][1], aa, B0.y); ffma2(acc[3][2], aa, B1.x); ffma2(acc[3][3], aa, B1.y);
                aa = pack2(a1.x, a1.x); ffma2(acc[4][0], aa, B0.x); ffma2(acc[4][1], aa, B0.y); ffma2(acc[4][2], aa, B1.x); ffma2(acc[4][3], aa, B1.y);
                aa = pack2(a1.y, a1.y); ffma2(acc[5][0], aa, B0.x); ffma2(acc[5][1], aa, B0.y); ffma2(acc[5][2], aa, B1.x); ffma2(acc[5][3], aa, B1.y);
                aa = pack2(a1.z, a1.z); ffma2(acc[6][0], aa, B0.x); ffma2(acc[6][1], aa, B0.y); ffma2(acc[6][2], aa, B1.x); ffma2(acc[6][3], aa, B1.y);
                aa = pack2(a1.w, a1.w); ffma2(acc[7][0], aa, B0.x); ffma2(acc[7][1], aa, B0.y); ffma2(acc[7][2], aa, B1.x); ffma2(acc[7][3], aa, B1.y);
            }
            if (k <= 6) bar_arrive(3 + buf);     // signal buffer free (none needed after)
        }

        // write outputs + psums into red area (buffer 1 region, producers are done)
        float* outp = &g_cat[((i * 4 + b) * 64) * HWN];
        float* red = smem + 8448;
#pragma unroll
        for (int oy = 0; oy < 8; oy++) {
            int o = ty * 8 + oy;
            float2 p0v = *(float2*)&acc[oy][0];
            float2 p1v = *(float2*)&acc[oy][1];
            float2 p2v = *(float2*)&acc[oy][2];
            float2 p3v = *(float2*)&acc[oy][3];
            *(float4*)&outp[o * HWN + p0 + tx * 4]      = make_float4(p0v.x, p0v.y, p1v.x, p1v.y);
            *(float4*)&outp[o * HWN + p0 + 64 + tx * 4] = make_float4(p2v.x, p2v.y, p3v.x, p3v.y);
            red[o * 16 + tx] = p0v.x + p0v.y + p1v.x + p1v.y + p2v.x + p2v.y + p3v.x + p3v.y;
        }
    }

    __syncthreads();
    if (tid < 64) {
        const float* red = smem + 8448;
        float s = 0.f;
#pragma unroll
        for (int t = 0; t < 16; t++) s += red[tid * 16 + t];
        g_bsums[((i * 4 + b) * 128 + row) * 64 + tid] = s;
    }
}

// ---------------- K4: SE MLP (tiny, one block) ----------------
__global__ void se_kernel(const float* __restrict__ w1, const float* __restrict__ b1,
                          const float* __restrict__ w2, const float* __restrict__ b2) {
    __shared__ float gm[4 * 256];
    __shared__ float h1[4 * 64];
    int tid = threadIdx.x;  // 256
    for (int idx = tid; idx < 1024; idx += 256) {
        int b = idx >> 8, ch = idx & 255;
        int i = ch >> 6, o = ch & 63;
        float s = 0.f;
        for (int r = 0; r < 128; r++)
            s += g_bsums[((i * 4 + b) * 128 + r) * 64 + o];
        gm[b * 256 + ch] = s * (1.f / 16384.f);
    }
    __syncthreads();
    {
        int b = tid >> 6, oc = tid & 63;
        float a = b1[oc];
        for (int ch = 0; ch < 256; ch++) a += w1[oc * 256 + ch] * gm[b * 256 + ch];
        h1[b * 64 + oc] = fmaxf(a, 0.f);
    }
    __syncthreads();
    for (int idx = tid; idx < 1024; idx += 256) {
        int b = idx >> 8, ch = idx & 255;
        float a = b2[ch];
        for (int oc = 0; oc < 64; oc++) a += w2[ch * 64 + oc] * h1[b * 64 + oc];
        g_gate[b * 256 + ch] = 1.f + 1.f / (1.f + expf(-a));
    }
}

// ---------------- K5: gated fuse + residual ----------------
__global__ void final_kernel(const float* __restrict__ x, float* __restrict__ out) {
    int idx = blockIdx.x * 256 + threadIdx.x;  // < 1048576 float4s
    int p4 = idx & 4095;
    int o  = (idx >> 12) & 63;
    int b  = idx >> 18;
    float4 a = ((const float4*)x)[idx];
#pragma unroll
    for (int i = 0; i < 4; i++) {
        float g = g_gate[b * 256 + i * 64 + o];
        float4 cv = ((const float4*)g_cat)[((i * 4 + b) * 64 + o) * 4096 + p4];
        a.x += g * cv.x;
        a.y += g * cv.y;
        a.z += g * cv.z;
        a.w += g * cv.w;
    }
    ((float4*)out)[idx] = a;
}

extern "C" void kernel_launch(void* const* d_in, const int* in_sizes, int n_in,
                              void* d_out, int out_size) {
    const float* x  = (const float*)d_in[0];
    const float* dw = (const float*)d_in[1];
    const float* ow = (const float*)d_in[2];
    const float* ob = (const float*)d_in[3];
    const float* w1 = (const float*)d_in[4];
    const float* b1 = (const float*)d_in[5];
    const float* w2 = (const float*)d_in[6];
    const float* b2 = (const float*)d_in[7];
    float* out = (float*)d_out;

    const int branch_smem = 2 * 8448 * 4;  // 67584 B (S double buffer)
    cudaFuncSetAttribute(branch_kernel, cudaFuncAttributeMaxDynamicSharedMemorySize, branch_smem);

    transpose_kernel<<<dim3(512, 2, 4), dim3(32, 8)>>>(x);
    dwt_kernel<<<576, 256>>>(dw);
    offset_kernel<<<dim3(64, 4, 4), 256>>>(x, ow, ob);
    branch_kernel<<<dim3(128, 4, 4), 256, branch_smem>>>();
    se_kernel<<<1, 256>>>(w1, b1, w2, b2);
    final_kernel<<<4096, 256>>>(x, out);
}

// round 8
// speedup vs baseline: 1.0364x; 1.0364x over previous
#include <cuda_runtime.h>

#define HH 128
#define WW 128
#define HWN 16384
#define BHW (4 * 16384)
#define BN 4
#define CN 64

typedef unsigned long long ull;

__device__ __constant__ int c_RATES[4] = {2, 3, 5, 9};

// Scratch (static device globals: allocation-free, graph-capturable)
__device__ float g_xhwc[BN * HWN * CN];            // [b][p][c]
__device__ float g_off[4 * 18 * BHW];              // [j][k2][b*HW+p]  planar
__device__ float g_dwt[4 * 9 * 64 * 64];           // [i][k][c][o]
__device__ float g_cat[4 * BN * CN * HWN];         // [i][b][o][p]
__device__ float g_bsums[4 * BN * 128 * 64];       // [i][b][row][o]
__device__ float g_gate[BN * 256];                 // 1 + sigmoid(...)

__device__ __forceinline__ ull pack2(float a, float b) {
    ull r;
    asm("mov.b64 %0, {%1, %2};" : "=l"(r) : "f"(a), "f"(b));
    return r;
}
__device__ __forceinline__ void ffma2(ull& d, ull a, ull b) {
    asm("fma.rn.f32x2 %0, %1, %2, %0;" : "+l"(d) : "l"(a), "l"(b));
}

// ---------------- K1: NCHW -> NHWC transpose of x ----------------
__global__ void transpose_kernel(const float* __restrict__ x) {
    __shared__ float tile[32][33];
    int b  = blockIdx.z;
    int p0 = blockIdx.x * 32;
    int c0 = blockIdx.y * 32;
    for (int i = threadIdx.y; i < 32; i += 8)
        tile[i][threadIdx.x] = x[(b * 64 + c0 + i) * HWN + p0 + threadIdx.x];
    __syncthreads();
    for (int i = threadIdx.y; i < 32; i += 8)
        g_xhwc[(b * HWN + p0 + i) * 64 + c0 + threadIdx.x] = tile[threadIdx.x][i];
}

// ---------------- K1b: dw (i,o,c,3,3) -> g_dwt [i][k][c][o] ----------------
__global__ void dwt_kernel(const float* __restrict__ dw) {
    int idx = blockIdx.x * 256 + threadIdx.x;  // < 147456
    int i  = idx / 36864;
    int r  = idx % 36864;
    int k  = r / 4096;
    int r2 = r & 4095;
    int c  = r2 >> 6;
    int o  = r2 & 63;
    g_dwt[idx] = dw[((i * 64 + o) * 64 + c) * 9 + k];
}

// ---------------- K2: offset conv (64 -> 18, dilated 3x3, relu), f32x2 ----------------
__global__ __launch_bounds__(256) void offset_kernel(const float* __restrict__ x,
                                                     const float* __restrict__ ow,
                                                     const float* __restrict__ ob) {
    __shared__ float ow_sh[9 * 64 * 20];
    int j = blockIdx.z, b = blockIdx.y;
    int rate = c_RATES[j];
    int tid = threadIdx.x;
    for (int idx = tid; idx < 9 * 64 * 20; idx += 256) {
        int k2 = idx % 20;
        int rest = idx / 20;
        int c = rest % 64;
        int t = rest / 64;
        ow_sh[idx] = (k2 < 18) ? ow[((j * 18 + k2) * 64 + c) * 9 + t] : 0.f;
    }
    __syncthreads();

    int p = blockIdx.x * 256 + tid;
    int y = p >> 7, xx = p & 127;
    ull acc2[10];
#pragma unroll
    for (int q = 0; q < 9; q++) acc2[q] = pack2(ob[j * 18 + 2 * q], ob[j * 18 + 2 * q + 1]);
    acc2[9] = 0ull;

    const float* xb = x + b * 64 * HWN;
    for (int t = 0; t < 9; t++) {
        int tyv = y + (t / 3 - 1) * rate;
        int txv = xx + (t % 3 - 1) * rate;
        if ((unsigned)tyv >= HH || (unsigned)txv >= WW) continue;
        const float* xp = xb + tyv * WW + txv;
#pragma unroll 4
        for (int c = 0; c < 64; c++) {
            float xc = xp[c * HWN];  // coalesced across warp
            ull xcc = pack2(xc, xc);
            const ull* wr = (const ull*)&ow_sh[(t * 64 + c) * 20];  // broadcast
#pragma unroll
            for (int q = 0; q < 10; q++) ffma2(acc2[q], wr[q], xcc);
        }
    }
    float* og = g_off + j * 18 * BHW + b * HWN + p;  // plane stride BHW, coalesced
#pragma unroll
    for (int q = 0; q < 9; q++) {
        float2 v = *(float2*)&acc2[q];
        og[(2 * q) * BHW]     = fmaxf(v.x, 0.f);
        og[(2 * q + 1) * BHW] = fmaxf(v.y, 0.f);
    }
}

// ---------------- K3: ping-pong pipelined deform sample + GEMM ----------------
// 256 threads = 2 warp-groups, each owns a 64-px half.
// Per k: each group interleaves gather(k+1) of its half with GEMM(k) of its half.
// S double-buffered; A single-buffered (staged per k behind barrier).
// S swizzle: phys(sp, c) = (sp + 4*(c>>2)) & 127
#define SPITCH 132

#define WEIGHTS_AND_PTRS(SP, KYR, KXR, OFY, OFX)                                   \
    float dy = __ldg((OFY) + (SP));                                                \
    float dx = __ldg((OFX) + (SP));                                                \
    float py = (float)(row + (KYR)) + dy;                                          \
    float px = (float)((SP) + (KXR)) + dx;                                         \
    float fy = floorf(py), fx = floorf(px);                                        \
    int iy0 = (int)fy, ix0 = (int)fx;                                              \
    float wy1 = py - fy, wx1 = px - fx;                                            \
    float wy0 = 1.f - wy1, wx0 = 1.f - wx1;                                        \
    bool vy0 = (unsigned)iy0 < HH, vy1 = (unsigned)(iy0 + 1) < HH;                 \
    bool vx0 = (unsigned)ix0 < WW, vx1 = (unsigned)(ix0 + 1) < WW;                 \
    float w00 = (vy0 && vx0) ? wy0 * wx0 : 0.f;                                    \
    float w01 = (vy0 && vx1) ? wy0 * wx1 : 0.f;                                    \
    float w10 = (vy1 && vx0) ? wy1 * wx0 : 0.f;                                    \
    float w11 = (vy1 && vx1) ? wy1 * wx1 : 0.f;                                    \
    ull w00d = pack2(w00, w00), w01d = pack2(w01, w01);                            \
    ull w10d = pack2(w10, w10), w11d = pack2(w11, w11);                            \
    int cy0 = min(max(iy0, 0), HH - 1), cy1 = min(max(iy0 + 1, 0), HH - 1);        \
    int cx0 = min(max(ix0, 0), WW - 1), cx1 = min(max(ix0 + 1, 0), WW - 1);        \
    const float* b00 = xb + (cy0 * WW + cx0) * 64;                                 \
    const float* b01 = xb + (cy0 * WW + cx1) * 64;                                 \
    const float* b10 = xb + (cy1 * WW + cx0) * 64;                                 \
    const float* b11 = xb + (cy1 * WW + cx1) * 64;

#define LERP_STS(T0, T1, T2, T3, CBASE, SHIFT, SP, SN)                             \
    {                                                                              \
        ull r0 = 0, r1 = 0;                                                        \
        ffma2(r0, w00d, (T0).x); ffma2(r1, w00d, (T0).y);                          \
        ffma2(r0, w01d, (T1).x); ffma2(r1, w01d, (T1).y);                          \
        ffma2(r0, w10d, (T2).x); ffma2(r1, w10d, (T2).y);                          \
        ffma2(r0, w11d, (T3).x); ffma2(r1, w11d, (T3).y);                          \
        float2 f0 = *(float2*)&r0, f1 = *(float2*)&r1;                             \
        float* d = &(SN)[(CBASE) * SPITCH + (((SP) + (SHIFT)) & 127)];             \
        d[0]          = f0.x;                                                      \
        d[SPITCH]     = f0.y;                                                      \
        d[2 * SPITCH] = f1.x;                                                      \
        d[3 * SPITCH] = f1.y;                                                      \
    }

#define GEMM8(CBASE)                                                               \
    _Pragma("unroll")                                                              \
    for (int cc = 0; cc < 8; cc++) {                                               \
        int c = (CBASE) + cc;                                                      \
        float4 a0 = *(const float4*)&A_sh[c * 64 + ty * 8];                        \
        float4 a1 = *(const float4*)&A_sh[c * 64 + ty * 8 + 4];                    \
        ulonglong2 B0 = *(const ulonglong2*)&Sc[c * SPITCH +                       \
                          ((grp * 64 + tx * 4 + (c & ~3)) & 127)];                 \
        ull aa;                                                                    \
        aa = pack2(a0.x, a0.x); ffma2(acc[0][0], aa, B0.x); ffma2(acc[0][1], aa, B0.y); \
        aa = pack2(a0.y, a0.y); ffma2(acc[1][0], aa, B0.x); ffma2(acc[1][1], aa, B0.y); \
        aa = pack2(a0.z, a0.z); ffma2(acc[2][0], aa, B0.x); ffma2(acc[2][1], aa, B0.y); \
        aa = pack2(a0.w, a0.w); ffma2(acc[3][0], aa, B0.x); ffma2(acc[3][1], aa, B0.y); \
        aa = pack2(a1.x, a1.x); ffma2(acc[4][0], aa, B0.x); ffma2(acc[4][1], aa, B0.y); \
        aa = pack2(a1.y, a1.y); ffma2(acc[5][0], aa, B0.x); ffma2(acc[5][1], aa, B0.y); \
        aa = pack2(a1.z, a1.z); ffma2(acc[6][0], aa, B0.x); ffma2(acc[6][1], aa, B0.y); \
        aa = pack2(a1.w, a1.w); ffma2(acc[7][0], aa, B0.x); ffma2(acc[7][1], aa, B0.y); \
    }

__global__ __launch_bounds__(256, 2) void branch_kernel() {
    extern __shared__ float smem[];
    float* A_sh = smem;  // 4096 floats; S[buf] = smem + 4096 + buf*8448

    int i = blockIdx.z, b = blockIdx.y, row = blockIdx.x;
    int p0 = row * 128;
    int j = (i + 3) & 3;
    int rate = c_RATES[i];
    int tid = threadIdx.x;
    int grp = tid >> 7;              // pixel half
    int gtid = tid & 127;
    int tx = gtid & 15, ty = gtid >> 4;
    int lane8 = gtid & 7;
    int pxi = (gtid >> 3) & 3;
    int warpg = gtid >> 5;           // 0..3 within group
    int ca = lane8 * 4;
    int sha = 4 * lane8;
    int shb = 4 * lane8 + 32;
    int pxbase = grp * 64 + warpg * 16 + pxi;

    const float* xb   = &g_xhwc[b * HWN * 64];
    const float* dwt  = &g_dwt[i * 9 * 4096];
    const float* offb = g_off + j * 18 * BHW + b * HWN + p0;

    ull acc[8][2];
#pragma unroll
    for (int oy = 0; oy < 8; oy++) { acc[oy][0] = 0ull; acc[oy][1] = 0ull; }

    // ---- prologue: gather k=0 (own half) into S buf 0 ----
    {
        float* Sn = smem + 4096;
        const float* offY = offb;
        const float* offX = offb + BHW;
        int kyr = -rate, kxr = -rate;
#pragma unroll 2
        for (int gg = 0; gg < 4; gg++) {
            int sp = pxbase + gg * 4;
            WEIGHTS_AND_PTRS(sp, kyr, kxr, offY, offX)
            {
                ulonglong2 t0 = *(const ulonglong2*)(b00 + ca);
                ulonglong2 t1 = *(const ulonglong2*)(b01 + ca);
                ulonglong2 t2 = *(const ulonglong2*)(b10 + ca);
                ulonglong2 t3 = *(const ulonglong2*)(b11 + ca);
                LERP_STS(t0, t1, t2, t3, ca, sha, sp, Sn)
            }
            {
                ulonglong2 t0 = *(const ulonglong2*)(b00 + ca + 32);
                ulonglong2 t1 = *(const ulonglong2*)(b01 + ca + 32);
                ulonglong2 t2 = *(const ulonglong2*)(b10 + ca + 32);
                ulonglong2 t3 = *(const ulonglong2*)(b11 + ca + 32);
                LERP_STS(t0, t1, t2, t3, ca + 32, shb, sp, Sn)
            }
        }
    }

    // ---- main loop: GEMM(k) on Sc, gather(k+1) into Sn, interleaved ----
    for (int k = 0; k < 9; k++) {
        __syncthreads();   // Sc ready (prev gather), A_sh free (prev GEMM done)
        // stage A[k]
        {
            const float4* asrc = (const float4*)(dwt + k * 4096);
            float4* adst = (float4*)A_sh;
            adst[tid]       = asrc[tid];
            adst[tid + 256] = asrc[tid + 256];
            adst[tid + 512] = asrc[tid + 512];
            adst[tid + 768] = asrc[tid + 768];
        }
        __syncthreads();   // A ready

        const float* Sc = smem + 4096 + (k & 1) * 8448;
        float* Sn = smem + 4096 + ((k + 1) & 1) * 8448;
        bool pf = (k < 8);
        int kn = k + 1;
        int kyr = (kn / 3 - 1) * rate;
        int kxr = (kn % 3 - 1) * rate;
        const float* offY = offb + (2 * kn) * BHW;
        const float* offX = offb + (2 * kn + 1) * BHW;

        for (int gg = 0; gg < 4; gg++) {
            int sp = pxbase + gg * 4;
            if (pf) {
                WEIGHTS_AND_PTRS(sp, kyr, kxr, offY, offX)
                ulonglong2 t0, t1, t2, t3;
                // chunk a loads in flight over first GEMM slice
                t0 = *(const ulonglong2*)(b00 + ca);
                t1 = *(const ulonglong2*)(b01 + ca);
                t2 = *(const ulonglong2*)(b10 + ca);
                t3 = *(const ulonglong2*)(b11 + ca);
                GEMM8(gg * 16)
                LERP_STS(t0, t1, t2, t3, ca, sha, sp, Sn)
                // chunk b loads in flight over second GEMM slice
                t0 = *(const ulonglong2*)(b00 + ca + 32);
                t1 = *(const ulonglong2*)(b01 + ca + 32);
                t2 = *(const ulonglong2*)(b10 + ca + 32);
                t3 = *(const ulonglong2*)(b11 + ca + 32);
                GEMM8(gg * 16 + 8)
                LERP_STS(t0, t1, t2, t3, ca + 32, shb, sp, Sn)
            } else {
                GEMM8(gg * 16)
                GEMM8(gg * 16 + 8)
            }
        }
    }

    // ---- epilogue: write outputs + per-row channel sums ----
    __syncthreads();
    float* outp = &g_cat[((i * 4 + b) * 64) * HWN];
    float* red = smem + 4096;  // reuse S area
#pragma unroll
    for (int oy = 0; oy < 8; oy++) {
        int o = ty * 8 + oy;
        float2 v0 = *(float2*)&acc[oy][0];
        float2 v1 = *(float2*)&acc[oy][1];
        *(float4*)&outp[o * HWN + p0 + grp * 64 + tx * 4] = make_float4(v0.x, v0.y, v1.x, v1.y);
        red[o * 32 + grp * 16 + tx] = v0.x + v0.y + v1.x + v1.y;
    }
    __syncthreads();
    if (tid < 64) {
        float s = 0.f;
#pragma unroll
        for (int t = 0; t < 32; t++) s += red[tid * 32 + t];
        g_bsums[((i * 4 + b) * 128 + row) * 64 + tid] = s;
    }
}

// ---------------- K4: SE MLP (tiny, one block) ----------------
__global__ void se_kernel(const float* __restrict__ w1, const float* __restrict__ b1,
                          const float* __restrict__ w2, const float* __restrict__ b2) {
    __shared__ float gm[4 * 256];
    __shared__ float h1[4 * 64];
    int tid = threadIdx.x;  // 256
    for (int idx = tid; idx < 1024; idx += 256) {
        int b = idx >> 8, ch = idx & 255;
        int i = ch >> 6, o = ch & 63;
        float s = 0.f;
        for (int r = 0; r < 128; r++)
            s += g_bsums[((i * 4 + b) * 128 + r) * 64 + o];
        gm[b * 256 + ch] = s * (1.f / 16384.f);
    }
    __syncthreads();
    {
        int b = tid >> 6, oc = tid & 63;
        float a = b1[oc];
        for (int ch = 0; ch < 256; ch++) a += w1[oc * 256 + ch] * gm[b * 256 + ch];
        h1[b * 64 + oc] = fmaxf(a, 0.f);
    }
    __syncthreads();
    for (int idx = tid; idx < 1024; idx += 256) {
        int b = idx >> 8, ch = idx & 255;
        float a = b2[ch];
        for (int oc = 0; oc < 64; oc++) a += w2[ch * 64 + oc] * h1[b * 64 + oc];
        g_gate[b * 256 + ch] = 1.f + 1.f / (1.f + expf(-a));
    }
}

// ---------------- K5: gated fuse + residual ----------------
__global__ void final_kernel(const float* __restrict__ x, float* __restrict__ out) {
    int idx = blockIdx.x * 256 + threadIdx.x;  // < 1048576 float4s
    int p4 = idx & 4095;
    int o  = (idx >> 12) & 63;
    int b  = idx >> 18;
    float4 a = ((const float4*)x)[idx];
#pragma unroll
    for (int i = 0; i < 4; i++) {
        float g = g_gate[b * 256 + i * 64 + o];
        float4 cv = ((const float4*)g_cat)[((i * 4 + b) * 64 + o) * 4096 + p4];
        a.x += g * cv.x;
        a.y += g * cv.y;
        a.z += g * cv.z;
        a.w += g * cv.w;
    }
    ((float4*)out)[idx] = a;
}

extern "C" void kernel_launch(void* const* d_in, const int* in_sizes, int n_in,
                              void* d_out, int out_size) {
    const float* x  = (const float*)d_in[0];
    const float* dw = (const float*)d_in[1];
    const float* ow = (const float*)d_in[2];
    const float* ob = (const float*)d_in[3];
    const float* w1 = (const float*)d_in[4];
    const float* b1 = (const float*)d_in[5];
    const float* w2 = (const float*)d_in[6];
    const float* b2 = (const float*)d_in[7];
    float* out = (float*)d_out;

    const int branch_smem = (4096 + 2 * 8448) * 4;  // 83968 B -> 2 blocks/SM
    cudaFuncSetAttribute(branch_kernel, cudaFuncAttributeMaxDynamicSharedMemorySize, branch_smem);

    transpose_kernel<<<dim3(512, 2, 4), dim3(32, 8)>>>(x);
    dwt_kernel<<<576, 256>>>(dw);
    offset_kernel<<<dim3(64, 4, 4), 256>>>(x, ow, ob);
    branch_kernel<<<dim3(128, 4, 4), 256, branch_smem>>>();
    se_kernel<<<1, 256>>>(w1, b1, w2, b2);
    final_kernel<<<4096, 256>>>(x, out);
}

// round 10
// speedup vs baseline: 1.2249x; 1.1819x over previous
#include <cuda_runtime.h>
#include <cuda_bf16.h>
#include <mma.h>
#include <cstdint>

using namespace nvcuda;

#define HH 128
#define WW 128
#define HWN 16384
#define BHW (4 * 16384)
#define BN 4
#define CN 64

typedef unsigned long long ull;

__device__ __constant__ int c_RATES[4] = {2, 3, 5, 9};

// Scratch (static device globals: allocation-free, graph-capturable)
__device__ float g_xhwc[BN * HWN * CN];             // [b][p][c]
__device__ float g_off[4 * 18 * BHW];               // [j][k2][b*HW+p] planar
__device__ __nv_bfloat16 g_dwb[4 * 9 * 9216];       // [i][k][hi 64x72 | lo 64x72]
__device__ float g_cat[4 * BN * CN * HWN];          // [i][b][o][p]
__device__ float g_bsum2[1024];                     // [(i*4+b)*64+o]
__device__ float g_gate[BN * 256];                  // 1 + sigmoid(...)

__device__ __forceinline__ ull pack2(float a, float b) {
    ull r;
    asm("mov.b64 %0, {%1, %2};" : "=l"(r) : "f"(a), "f"(b));
    return r;
}
__device__ __forceinline__ void ffma2(ull& d, ull a, ull b) {
    asm("fma.rn.f32x2 %0, %1, %2, %0;" : "+l"(d) : "l"(a), "l"(b));
}
// split packed f32 pair (fx -> lower half, fy -> upper half) into bf16x2 hi + lo residual
__device__ __forceinline__ void bf16_split(float fx, float fy, unsigned& h, unsigned& l) {
    asm("cvt.rn.bf16x2.f32 %0, %1, %2;" : "=r"(h) : "f"(fy), "f"(fx));
    float hy = __uint_as_float(h & 0xFFFF0000u);
    float hx = __uint_as_float(h << 16);
    float ly = fy - hy, lx = fx - hx;
    asm("cvt.rn.bf16x2.f32 %0, %1, %2;" : "=r"(l) : "f"(ly), "f"(lx));
}

// ---------------- K1: NCHW -> NHWC transpose of x ----------------
__global__ void transpose_kernel(const float* __restrict__ x) {
    __shared__ float tile[32][33];
    int b  = blockIdx.z;
    int p0 = blockIdx.x * 32;
    int c0 = blockIdx.y * 32;
    for (int i = threadIdx.y; i < 32; i += 8)
        tile[i][threadIdx.x] = x[(b * 64 + c0 + i) * HWN + p0 + threadIdx.x];
    __syncthreads();
    for (int i = threadIdx.y; i < 32; i += 8)
        g_xhwc[(b * HWN + p0 + i) * 64 + c0 + threadIdx.x] = tile[threadIdx.x][i];
}

// ---------------- K1b: dw -> bf16 hi/lo A tiles [o][c], pitch 72 ----------------
__global__ void dwb_kernel(const float* __restrict__ dw) {
    int idx = blockIdx.x * 256 + threadIdx.x;  // < 73728 = 4*9*64*32
    int i  = idx / 18432;
    int r  = idx % 18432;
    int k  = r / 2048;
    int r2 = r % 2048;
    int o  = r2 >> 5;
    int e  = r2 & 31;
    int c  = e * 2;
    float v0 = dw[((i * 64 + o) * 64 + c) * 9 + k];
    float v1 = dw[((i * 64 + o) * 64 + c + 1) * 9 + k];
    unsigned h, l;
    bf16_split(v0, v1, h, l);
    __nv_bfloat16* base = g_dwb + (size_t)(i * 9 + k) * 9216;
    *(unsigned*)(base + o * 72 + c)        = h;   // hi tile
    *(unsigned*)(base + 4608 + o * 72 + c) = l;   // lo tile
}

// ---------------- K2: offset conv (64 -> 18, dilated 3x3, relu), f32x2 ----------------
__global__ __launch_bounds__(256) void offset_kernel(const float* __restrict__ x,
                                                     const float* __restrict__ ow,
                                                     const float* __restrict__ ob) {
    __shared__ float ow_sh[9 * 64 * 20];
    int j = blockIdx.z, b = blockIdx.y;
    int rate = c_RATES[j];
    int tid = threadIdx.x;
    for (int idx = tid; idx < 9 * 64 * 20; idx += 256) {
        int k2 = idx % 20;
        int rest = idx / 20;
        int c = rest % 64;
        int t = rest / 64;
        ow_sh[idx] = (k2 < 18) ? ow[((j * 18 + k2) * 64 + c) * 9 + t] : 0.f;
    }
    __syncthreads();

    int p = blockIdx.x * 256 + tid;
    int y = p >> 7, xx = p & 127;
    ull acc2[10];
#pragma unroll
    for (int q = 0; q < 9; q++) acc2[q] = pack2(ob[j * 18 + 2 * q], ob[j * 18 + 2 * q + 1]);
    acc2[9] = 0ull;

    const float* xb = x + b * 64 * HWN;
    for (int t = 0; t < 9; t++) {
        int tyv = y + (t / 3 - 1) * rate;
        int txv = xx + (t % 3 - 1) * rate;
        if ((unsigned)tyv >= HH || (unsigned)txv >= WW) continue;
        const float* xp = xb + tyv * WW + txv;
#pragma unroll 4
        for (int c = 0; c < 64; c++) {
            float xc = xp[c * HWN];
            ull xcc = pack2(xc, xc);
            const ull* wr = (const ull*)&ow_sh[(t * 64 + c) * 20];
#pragma unroll
            for (int q = 0; q < 10; q++) ffma2(acc2[q], wr[q], xcc);
        }
    }
    float* og = g_off + j * 18 * BHW + b * HWN + p;
#pragma unroll
    for (int q = 0; q < 9; q++) {
        float2 v = *(float2*)&acc2[q];
        og[(2 * q) * BHW]     = fmaxf(v.x, 0.f);
        og[(2 * q + 1) * BHW] = fmaxf(v.y, 0.f);
    }
}

// ---------------- K3: gather (bf16 split) + WMMA tensor GEMM per branch ----------------
// tile = 1 image row: OUT[64o,128px] = sum_k DW_k[64o,64c] @ S_k[64c,128px]
// 3-term split: AhBh + AhBl + AlBh.  8 warps = 4 o-tiles x 2 px-halves.
// S in smem as [px][c] pitch 72 (col_major B frags); A frags loaded from global (L1-hot).
#define SPIT 72
__global__ __launch_bounds__(256) void branch_kernel() {
    __shared__ __nv_bfloat16 Shi[128 * SPIT];
    __shared__ __nv_bfloat16 Slo[128 * SPIT];

    int i = blockIdx.z, b = blockIdx.y, row = blockIdx.x;
    int p0 = row * 128;
    int j = (i + 3) & 3;
    int rate = c_RATES[i];
    int tid = threadIdx.x;
    int warp = tid >> 5;
    int otile = warp & 3, ph = warp >> 2;
    int lane8 = tid & 7;
    int ca = lane8 * 4;

    const float* xb   = &g_xhwc[b * HWN * 64];
    const float* offb = g_off + j * 18 * BHW + b * HWN + p0;

    wmma::fragment<wmma::accumulator, 16, 16, 16, float> acc[4];
#pragma unroll
    for (int nt = 0; nt < 4; nt++) wmma::fill_fragment(acc[nt], 0.f);

    for (int k = 0; k < 9; k++) {
        __syncthreads();
        // ---- gather tap k: 4 passes x 32 px; thread owns pixel sp, chunks ca & ca+32 ----
        int kyr = (k / 3 - 1) * rate;
        int kxr = (k % 3 - 1) * rate;
        const float* offY = offb + (2 * k) * BHW;
        const float* offX = offb + (2 * k + 1) * BHW;
#pragma unroll 2
        for (int pass = 0; pass < 4; pass++) {
            int sp = pass * 32 + (tid >> 3);
            float dy = __ldg(offY + sp);
            float dx = __ldg(offX + sp);
            float py = (float)(row + kyr) + dy;
            float px = (float)(sp + kxr) + dx;
            float fy = floorf(py), fx = floorf(px);
            int iy0 = (int)fy, ix0 = (int)fx;
            float wy1 = py - fy, wx1 = px - fx;
            float wy0 = 1.f - wy1, wx0 = 1.f - wx1;
            bool vy0 = (unsigned)iy0 < HH, vy1 = (unsigned)(iy0 + 1) < HH;
            bool vx0 = (unsigned)ix0 < WW, vx1 = (unsigned)(ix0 + 1) < WW;
            float w00 = (vy0 && vx0) ? wy0 * wx0 : 0.f;
            float w01 = (vy0 && vx1) ? wy0 * wx1 : 0.f;
            float w10 = (vy1 && vx0) ? wy1 * wx0 : 0.f;
            float w11 = (vy1 && vx1) ? wy1 * wx1 : 0.f;
            ull w00d = pack2(w00, w00), w01d = pack2(w01, w01);
            ull w10d = pack2(w10, w10), w11d = pack2(w11, w11);
            int cy0 = min(max(iy0, 0), HH - 1), cy1 = min(max(iy0 + 1, 0), HH - 1);
            int cx0 = min(max(ix0, 0), WW - 1), cx1 = min(max(ix0 + 1, 0), WW - 1);
            const float* b00 = xb + (cy0 * WW + cx0) * 64;
            const float* b01 = xb + (cy0 * WW + cx1) * 64;
            const float* b10 = xb + (cy1 * WW + cx0) * 64;
            const float* b11 = xb + (cy1 * WW + cx1) * 64;
#pragma unroll
            for (int half = 0; half < 2; half++) {
                int cc = ca + half * 32;
                ulonglong2 t00 = *(const ulonglong2*)(b00 + cc);
                ulonglong2 t01 = *(const ulonglong2*)(b01 + cc);
                ulonglong2 t10 = *(const ulonglong2*)(b10 + cc);
                ulonglong2 t11 = *(const ulonglong2*)(b11 + cc);
                ull r0 = 0, r1 = 0;
                ffma2(r0, w00d, t00.x); ffma2(r1, w00d, t00.y);
                ffma2(r0, w01d, t01.x); ffma2(r1, w01d, t01.y);
                ffma2(r0, w10d, t10.x); ffma2(r1, w10d, t10.y);
                ffma2(r0, w11d, t11.x); ffma2(r1, w11d, t11.y);
                float2 f0 = *(float2*)&r0, f1 = *(float2*)&r1;
                unsigned h0, l0, h1, l1;
                bf16_split(f0.x, f0.y, h0, l0);
                bf16_split(f1.x, f1.y, h1, l1);
                unsigned* dh = (unsigned*)(Shi + sp * SPIT + cc);
                dh[0] = h0; dh[1] = h1;
                unsigned* dl = (unsigned*)(Slo + sp * SPIT + cc);
                dl[0] = l0; dl[1] = l1;
            }
        }
        __syncthreads();

        // ---- tensor GEMM for tap k ----
        const __nv_bfloat16* Ahg = g_dwb + (size_t)(i * 9 + k) * 9216;
        const __nv_bfloat16* Alg = Ahg + 4608;
#pragma unroll
        for (int kc = 0; kc < 4; kc++) {
            wmma::fragment<wmma::matrix_a, 16, 16, 16, __nv_bfloat16, wmma::row_major> Ah, Al;
            wmma::load_matrix_sync(Ah, Ahg + otile * 16 * SPIT + kc * 16, SPIT);
            wmma::load_matrix_sync(Al, Alg + otile * 16 * SPIT + kc * 16, SPIT);
#pragma unroll
            for (int nt = 0; nt < 4; nt++) {
                wmma::fragment<wmma::matrix_b, 16, 16, 16, __nv_bfloat16, wmma::col_major> Bh, Bl;
                int pxb = ph * 64 + nt * 16;
                wmma::load_matrix_sync(Bh, Shi + pxb * SPIT + kc * 16, SPIT);
                wmma::load_matrix_sync(Bl, Slo + pxb * SPIT + kc * 16, SPIT);
                wmma::mma_sync(acc[nt], Ah, Bh, acc[nt]);
                wmma::mma_sync(acc[nt], Ah, Bl, acc[nt]);
                wmma::mma_sync(acc[nt], Al, Bh, acc[nt]);
            }
        }
    }

    // ---- epilogue: store output tiles directly to g_cat ----
    float* outp = &g_cat[((i * 4 + b) * 64) * HWN];
#pragma unroll
    for (int nt = 0; nt < 4; nt++)
        wmma::store_matrix_sync(outp + (otile * 16) * HWN + p0 + ph * 64 + nt * 16,
                                acc[nt], HWN, wmma::mem_row_major);
}

// ---------------- K3b: per-(i,b,o) channel sums for SE ----------------
__global__ void reduce_kernel() {
    __shared__ float sred[256];
    int idx = blockIdx.x;  // 0..1023
    const float4* src = (const float4*)(g_cat + (size_t)idx * HWN);
    float s = 0.f;
    for (int t = threadIdx.x; t < 4096; t += 256) {
        float4 v = src[t];
        s += v.x + v.y + v.z + v.w;
    }
    sred[threadIdx.x] = s;
    __syncthreads();
    for (int st = 128; st > 0; st >>= 1) {
        if (threadIdx.x < st) sred[threadIdx.x] += sred[threadIdx.x + st];
        __syncthreads();
    }
    if (threadIdx.x == 0) g_bsum2[idx] = sred[0];
}

// ---------------- K4: SE MLP (tiny, one block) ----------------
__global__ void se_kernel(const float* __restrict__ w1, const float* __restrict__ b1,
                          const float* __restrict__ w2, const float* __restrict__ b2) {
    __shared__ float gm[4 * 256];
    __shared__ float h1[4 * 64];
    int tid = threadIdx.x;  // 256
    for (int idx = tid; idx < 1024; idx += 256) {
        int b = idx >> 8, ch = idx & 255;
        gm[b * 256 + ch] = g_bsum2[((ch >> 6) * 4 + b) * 64 + (ch & 63)] * (1.f / 16384.f);
    }
    __syncthreads();
    {
        int b = tid >> 6, oc = tid & 63;
        float a = b1[oc];
        for (int ch = 0; ch < 256; ch++) a += w1[oc * 256 + ch] * gm[b * 256 + ch];
        h1[b * 64 + oc] = fmaxf(a, 0.f);
    }
    __syncthreads();
    for (int idx = tid; idx < 1024; idx += 256) {
        int b = idx >> 8, ch = idx & 255;
        float a = b2[ch];
        for (int oc = 0; oc < 64; oc++) a += w2[ch * 64 + oc] * h1[b * 64 + oc];
        g_gate[b * 256 + ch] = 1.f + 1.f / (1.f + expf(-a));
    }
}

// ---------------- K5: gated fuse + residual ----------------
__global__ void final_kernel(const float* __restrict__ x, float* __restrict__ out) {
    int idx = blockIdx.x * 256 + threadIdx.x;  // < 1048576 float4s
    int p4 = idx & 4095;
    int o  = (idx >> 12) & 63;
    int b  = idx >> 18;
    float4 a = ((const float4*)x)[idx];
#pragma unroll
    for (int i = 0; i < 4; i++) {
        float g = g_gate[b * 256 + i * 64 + o];
        float4 cv = ((const float4*)g_cat)[((i * 4 + b) * 64 + o) * 4096 + p4];
        a.x += g * cv.x;
        a.y += g * cv.y;
        a.z += g * cv.z;
        a.w += g * cv.w;
    }
    ((float4*)out)[idx] = a;
}

extern "C" void kernel_launch(void* const* d_in, const int* in_sizes, int n_in,
                              void* d_out, int out_size) {
    const float* x  = (const float*)d_in[0];
    const float* dw = (const float*)d_in[1];
    const float* ow = (const float*)d_in[2];
    const float* ob = (const float*)d_in[3];
    const float* w1 = (const float*)d_in[4];
    const float* b1 = (const float*)d_in[5];
    const float* w2 = (const float*)d_in[6];
    const float* b2 = (const float*)d_in[7];
    float* out = (float*)d_out;

    transpose_kernel<<<dim3(512, 2, 4), dim3(32, 8)>>>(x);
    dwb_kernel<<<288, 256>>>(dw);
    offset_kernel<<<dim3(64, 4, 4), 256>>>(x, ow, ob);
    branch_kernel<<<dim3(128, 4, 4), 256>>>();
    reduce_kernel<<<1024, 256>>>();
    se_kernel<<<1, 256>>>(w1, b1, w2, b2);
    final_kernel<<<4096, 256>>>(x, out);
}

// round 11
// speedup vs baseline: 1.2251x; 1.0001x over previous
#include <cuda_runtime.h>
#include <cuda_bf16.h>
#include <mma.h>
#include <cstdint>

using namespace nvcuda;

#define HH 128
#define WW 128
#define HWN 16384
#define BHW (4 * 16384)
#define BN 4
#define CN 64

typedef unsigned long long ull;

__device__ __constant__ int c_RATES[4] = {2, 3, 5, 9};

// Scratch (static device globals: allocation-free, graph-capturable)
__device__ float g_xhwc[BN * HWN * CN];             // [b][p][c]
__device__ float g_off[4 * 18 * BHW];               // [j][k2][b*HW+p] planar
__device__ __nv_bfloat16 g_dwb[4 * 9 * 9216];       // [i][k][hi 64x72 | lo 64x72]
__device__ float g_cat[4 * BN * CN * HWN];          // [i][b][o][p]
__device__ float g_bsum2[1024];                     // [(i*4+b)*64+o]
__device__ float g_gate[BN * 256];                  // 1 + sigmoid(...)

__device__ __forceinline__ ull pack2(float a, float b) {
    ull r;
    asm("mov.b64 %0, {%1, %2};" : "=l"(r) : "f"(a), "f"(b));
    return r;
}
__device__ __forceinline__ void ffma2(ull& d, ull a, ull b) {
    asm("fma.rn.f32x2 %0, %1, %2, %0;" : "+l"(d) : "l"(a), "l"(b));
}
// split packed f32 pair (fx -> lower half, fy -> upper half) into bf16x2 hi + lo residual
__device__ __forceinline__ void bf16_split(float fx, float fy, unsigned& h, unsigned& l) {
    asm("cvt.rn.bf16x2.f32 %0, %1, %2;" : "=r"(h) : "f"(fy), "f"(fx));
    float hy = __uint_as_float(h & 0xFFFF0000u);
    float hx = __uint_as_float(h << 16);
    float ly = fy - hy, lx = fx - hx;
    asm("cvt.rn.bf16x2.f32 %0, %1, %2;" : "=r"(l) : "f"(ly), "f"(lx));
}

// ---------------- K1: NCHW -> NHWC transpose of x ----------------
__global__ void transpose_kernel(const float* __restrict__ x) {
    __shared__ float tile[32][33];
    int b  = blockIdx.z;
    int p0 = blockIdx.x * 32;
    int c0 = blockIdx.y * 32;
    for (int i = threadIdx.y; i < 32; i += 8)
        tile[i][threadIdx.x] = x[(b * 64 + c0 + i) * HWN + p0 + threadIdx.x];
    __syncthreads();
    for (int i = threadIdx.y; i < 32; i += 8)
        g_xhwc[(b * HWN + p0 + i) * 64 + c0 + threadIdx.x] = tile[threadIdx.x][i];
}

// ---------------- K1b: dw -> bf16 hi/lo A tiles [o][c], pitch 72 ----------------
__global__ void dwb_kernel(const float* __restrict__ dw) {
    int idx = blockIdx.x * 256 + threadIdx.x;  // < 73728 = 4*9*64*32
    int i  = idx / 18432;
    int r  = idx % 18432;
    int k  = r / 2048;
    int r2 = r % 2048;
    int o  = r2 >> 5;
    int e  = r2 & 31;
    int c  = e * 2;
    float v0 = dw[((i * 64 + o) * 64 + c) * 9 + k];
    float v1 = dw[((i * 64 + o) * 64 + c + 1) * 9 + k];
    unsigned h, l;
    bf16_split(v0, v1, h, l);
    __nv_bfloat16* base = g_dwb + (size_t)(i * 9 + k) * 9216;
    *(unsigned*)(base + o * 72 + c)        = h;   // hi tile
    *(unsigned*)(base + 4608 + o * 72 + c) = l;   // lo tile
}

// ---------------- K2: offset conv (64 -> 18, dilated 3x3, relu), f32x2 ----------------
__global__ __launch_bounds__(256) void offset_kernel(const float* __restrict__ x,
                                                     const float* __restrict__ ow,
                                                     const float* __restrict__ ob) {
    __shared__ float ow_sh[9 * 64 * 20];
    int j = blockIdx.z, b = blockIdx.y;
    int rate = c_RATES[j];
    int tid = threadIdx.x;
    for (int idx = tid; idx < 9 * 64 * 20; idx += 256) {
        int k2 = idx % 20;
        int rest = idx / 20;
        int c = rest % 64;
        int t = rest / 64;
        ow_sh[idx] = (k2 < 18) ? ow[((j * 18 + k2) * 64 + c) * 9 + t] : 0.f;
    }
    __syncthreads();

    int p = blockIdx.x * 256 + tid;
    int y = p >> 7, xx = p & 127;
    ull acc2[10];
#pragma unroll
    for (int q = 0; q < 9; q++) acc2[q] = pack2(ob[j * 18 + 2 * q], ob[j * 18 + 2 * q + 1]);
    acc2[9] = 0ull;

    const float* xb = x + b * 64 * HWN;
    for (int t = 0; t < 9; t++) {
        int tyv = y + (t / 3 - 1) * rate;
        int txv = xx + (t % 3 - 1) * rate;
        if ((unsigned)tyv >= HH || (unsigned)txv >= WW) continue;
        const float* xp = xb + tyv * WW + txv;
#pragma unroll 4
        for (int c = 0; c < 64; c++) {
            float xc = xp[c * HWN];
            ull xcc = pack2(xc, xc);
            const ull* wr = (const ull*)&ow_sh[(t * 64 + c) * 20];
#pragma unroll
            for (int q = 0; q < 10; q++) ffma2(acc2[q], wr[q], xcc);
        }
    }
    float* og = g_off + j * 18 * BHW + b * HWN + p;
#pragma unroll
    for (int q = 0; q < 9; q++) {
        float2 v = *(float2*)&acc2[q];
        og[(2 * q) * BHW]     = fmaxf(v.x, 0.f);
        og[(2 * q + 1) * BHW] = fmaxf(v.y, 0.f);
    }
}

// ---------------- K3: pipelined gather (bf16 split) + WMMA GEMM per branch ----------------
// tile = 1 image row: OUT[64o,128px] = sum_k DW_k[64o,64c] @ S_k[64c,128px]
// S hi/lo double-buffered; gather(k+1) interleaved with GEMM(k) at pass/kc granularity.
#define SPIT 72
#define SBUF (128 * SPIT)

#define TAP_WEIGHTS(SP, KYR, KXR, OFY, OFX)                                        \
    {                                                                              \
        float dy = __ldg((OFY) + (SP));                                            \
        float dx = __ldg((OFX) + (SP));                                            \
        float py = (float)(row + (KYR)) + dy;                                      \
        float px = (float)((SP) + (KXR)) + dx;                                     \
        float fy = floorf(py), fx = floorf(px);                                    \
        int iy0 = (int)fy, ix0 = (int)fx;                                          \
        float wy1 = py - fy, wx1 = px - fx;                                        \
        float wy0 = 1.f - wy1, wx0 = 1.f - wx1;                                    \
        bool vy0 = (unsigned)iy0 < HH, vy1 = (unsigned)(iy0 + 1) < HH;             \
        bool vx0 = (unsigned)ix0 < WW, vx1 = (unsigned)(ix0 + 1) < WW;             \
        float w00 = (vy0 && vx0) ? wy0 * wx0 : 0.f;                                \
        float w01 = (vy0 && vx1) ? wy0 * wx1 : 0.f;                                \
        float w10 = (vy1 && vx0) ? wy1 * wx0 : 0.f;                                \
        float w11 = (vy1 && vx1) ? wy1 * wx1 : 0.f;                                \
        w00d = pack2(w00, w00); w01d = pack2(w01, w01);                            \
        w10d = pack2(w10, w10); w11d = pack2(w11, w11);                            \
        int cy0 = min(max(iy0, 0), HH - 1), cy1 = min(max(iy0 + 1, 0), HH - 1);    \
        int cx0 = min(max(ix0, 0), WW - 1), cx1 = min(max(ix0 + 1, 0), WW - 1);    \
        b00 = xb + (cy0 * WW + cx0) * 64;                                          \
        b01 = xb + (cy0 * WW + cx1) * 64;                                          \
        b10 = xb + (cy1 * WW + cx0) * 64;                                          \
        b11 = xb + (cy1 * WW + cx1) * 64;                                          \
    }

#define TAP_LOADS(CC)                                                              \
    {                                                                              \
        t0 = *(const ulonglong2*)(b00 + (CC));                                     \
        t1 = *(const ulonglong2*)(b01 + (CC));                                     \
        t2 = *(const ulonglong2*)(b10 + (CC));                                     \
        t3 = *(const ulonglong2*)(b11 + (CC));                                     \
    }

#define LERP_SPLIT_STS(CC, SP, HI, LO)                                             \
    {                                                                              \
        ull r0 = 0, r1 = 0;                                                        \
        ffma2(r0, w00d, t0.x); ffma2(r1, w00d, t0.y);                              \
        ffma2(r0, w01d, t1.x); ffma2(r1, w01d, t1.y);                              \
        ffma2(r0, w10d, t2.x); ffma2(r1, w10d, t2.y);                              \
        ffma2(r0, w11d, t3.x); ffma2(r1, w11d, t3.y);                              \
        float2 f0 = *(float2*)&r0, f1 = *(float2*)&r1;                             \
        unsigned h0, l0, h1, l1;                                                   \
        bf16_split(f0.x, f0.y, h0, l0);                                            \
        bf16_split(f1.x, f1.y, h1, l1);                                            \
        unsigned* dh = (unsigned*)((HI) + (SP) * SPIT + (CC));                     \
        dh[0] = h0; dh[1] = h1;                                                    \
        unsigned* dl = (unsigned*)((LO) + (SP) * SPIT + (CC));                     \
        dl[0] = l0; dl[1] = l1;                                                    \
    }

#define GEMM_NT(NT)                                                                \
    {                                                                              \
        wmma::fragment<wmma::matrix_b, 16, 16, 16, __nv_bfloat16, wmma::col_major> Bh, Bl; \
        int pxb = ph * 64 + (NT) * 16;                                             \
        wmma::load_matrix_sync(Bh, ShiC + pxb * SPIT + pass * 16, SPIT);           \
        wmma::load_matrix_sync(Bl, SloC + pxb * SPIT + pass * 16, SPIT);           \
        wmma::mma_sync(acc[NT], Ah, Bh, acc[NT]);                                  \
        wmma::mma_sync(acc[NT], Ah, Bl, acc[NT]);                                  \
        wmma::mma_sync(acc[NT], Al, Bh, acc[NT]);                                  \
    }

__global__ __launch_bounds__(256, 2) void branch_kernel() {
    extern __shared__ __nv_bfloat16 sm[];
    // layout: Shi[0], Shi[1], Slo[0], Slo[1] each SBUF

    int i = blockIdx.z, b = blockIdx.y, row = blockIdx.x;
    int p0 = row * 128;
    int j = (i + 3) & 3;
    int rate = c_RATES[i];
    int tid = threadIdx.x;
    int warp = tid >> 5;
    int otile = warp & 3, ph = warp >> 2;
    int lane8 = tid & 7;
    int ca = lane8 * 4;

    const float* xb   = &g_xhwc[b * HWN * 64];
    const float* offb = g_off + j * 18 * BHW + b * HWN + p0;

    wmma::fragment<wmma::accumulator, 16, 16, 16, float> acc[4];
#pragma unroll
    for (int nt = 0; nt < 4; nt++) wmma::fill_fragment(acc[nt], 0.f);

    // ---- prologue: gather tap 0 into buffer 0 ----
    {
        __nv_bfloat16* Hn = sm;
        __nv_bfloat16* Ln = sm + 2 * SBUF;
        const float* offY = offb;
        const float* offX = offb + BHW;
        int kyr = -rate, kxr = -rate;
#pragma unroll 2
        for (int pass = 0; pass < 4; pass++) {
            int sp = pass * 32 + (tid >> 3);
            ull w00d, w01d, w10d, w11d;
            const float *b00, *b01, *b10, *b11;
            ulonglong2 t0, t1, t2, t3;
            TAP_WEIGHTS(sp, kyr, kxr, offY, offX)
            TAP_LOADS(ca)
            LERP_SPLIT_STS(ca, sp, Hn, Ln)
            TAP_LOADS(ca + 32)
            LERP_SPLIT_STS(ca + 32, sp, Hn, Ln)
        }
    }

    // ---- main loop: GEMM(k) from cur buffer, gather(k+1) into next ----
    for (int k = 0; k < 9; k++) {
        __syncthreads();
        const __nv_bfloat16* ShiC = sm + (k & 1) * SBUF;
        const __nv_bfloat16* SloC = sm + 2 * SBUF + (k & 1) * SBUF;
        __nv_bfloat16* Hn = sm + ((k + 1) & 1) * SBUF;
        __nv_bfloat16* Ln = sm + 2 * SBUF + ((k + 1) & 1) * SBUF;
        bool pf = (k < 8);
        int kn = k + 1;
        int kyr = (kn / 3 - 1) * rate;
        int kxr = (kn % 3 - 1) * rate;
        const float* offY = offb + (2 * kn) * BHW;
        const float* offX = offb + (2 * kn + 1) * BHW;
        const __nv_bfloat16* Ahg = g_dwb + (size_t)(i * 9 + k) * 9216;
        const __nv_bfloat16* Alg = Ahg + 4608;

#pragma unroll
        for (int pass = 0; pass < 4; pass++) {
            int sp = pass * 32 + (tid >> 3);
            ull w00d = 0, w01d = 0, w10d = 0, w11d = 0;
            const float *b00 = xb, *b01 = xb, *b10 = xb, *b11 = xb;
            ulonglong2 t0, t1, t2, t3;
            if (pf) {
                TAP_WEIGHTS(sp, kyr, kxr, offY, offX)
                TAP_LOADS(ca)           // chunk-a taps in flight
            }
            wmma::fragment<wmma::matrix_a, 16, 16, 16, __nv_bfloat16, wmma::row_major> Ah, Al;
            wmma::load_matrix_sync(Ah, Ahg + otile * 16 * SPIT + pass * 16, SPIT);
            wmma::load_matrix_sync(Al, Alg + otile * 16 * SPIT + pass * 16, SPIT);
            GEMM_NT(0)
            GEMM_NT(1)
            if (pf) {
                LERP_SPLIT_STS(ca, sp, Hn, Ln)
                TAP_LOADS(ca + 32)      // chunk-b taps in flight
            }
            GEMM_NT(2)
            GEMM_NT(3)
            if (pf) {
                LERP_SPLIT_STS(ca + 32, sp, Hn, Ln)
            }
        }
    }

    // ---- epilogue: store output tiles directly to g_cat ----
    float* outp = &g_cat[((i * 4 + b) * 64) * HWN];
#pragma unroll
    for (int nt = 0; nt < 4; nt++)
        wmma::store_matrix_sync(outp + (otile * 16) * HWN + p0 + ph * 64 + nt * 16,
                                acc[nt], HWN, wmma::mem_row_major);
}

// ---------------- K3b: per-(i,b,o) channel sums for SE ----------------
__global__ void reduce_kernel() {
    __shared__ float sred[256];
    int idx = blockIdx.x;  // 0..1023
    const float4* src = (const float4*)(g_cat + (size_t)idx * HWN);
    float s = 0.f;
    for (int t = threadIdx.x; t < 4096; t += 256) {
        float4 v = src[t];
        s += v.x + v.y + v.z + v.w;
    }
    sred[threadIdx.x] = s;
    __syncthreads();
    for (int st = 128; st > 0; st >>= 1) {
        if (threadIdx.x < st) sred[threadIdx.x] += sred[threadIdx.x + st];
        __syncthreads();
    }
    if (threadIdx.x == 0) g_bsum2[idx] = sred[0];
}

// ---------------- K4: SE MLP (tiny, one block) ----------------
__global__ void se_kernel(const float* __restrict__ w1, const float* __restrict__ b1,
                          const float* __restrict__ w2, const float* __restrict__ b2) {
    __shared__ float gm[4 * 256];
    __shared__ float h1[4 * 64];
    int tid = threadIdx.x;  // 256
    for (int idx = tid; idx < 1024; idx += 256) {
        int b = idx >> 8, ch = idx & 255;
        gm[b * 256 + ch] = g_bsum2[((ch >> 6) * 4 + b) * 64 + (ch & 63)] * (1.f / 16384.f);
    }
    __syncthreads();
    {
        int b = tid >> 6, oc = tid & 63;
        float a = b1[oc];
        for (int ch = 0; ch < 256; ch++) a += w1[oc * 256 + ch] * gm[b * 256 + ch];
        h1[b * 64 + oc] = fmaxf(a, 0.f);
    }
    __syncthreads();
    for (int idx = tid; idx < 1024; idx += 256) {
        int b = idx >> 8, ch = idx & 255;
        float a = b2[ch];
        for (int oc = 0; oc < 64; oc++) a += w2[ch * 64 + oc] * h1[b * 64 + oc];
        g_gate[b * 256 + ch] = 1.f + 1.f / (1.f + expf(-a));
    }
}

// ---------------- K5: gated fuse + residual ----------------
__global__ void final_kernel(const float* __restrict__ x, float* __restrict__ out) {
    int idx = blockIdx.x * 256 + threadIdx.x;  // < 1048576 float4s
    int p4 = idx & 4095;
    int o  = (idx >> 12) & 63;
    int b  = idx >> 18;
    float4 a = ((const float4*)x)[idx];
#pragma unroll
    for (int i = 0; i < 4; i++) {
        float g = g_gate[b * 256 + i * 64 + o];
        float4 cv = ((const float4*)g_cat)[((i * 4 + b) * 64 + o) * 4096 + p4];
        a.x += g * cv.x;
        a.y += g * cv.y;
        a.z += g * cv.z;
        a.w += g * cv.w;
    }
    ((float4*)out)[idx] = a;
}

extern "C" void kernel_launch(void* const* d_in, const int* in_sizes, int n_in,
                              void* d_out, int out_size) {
    const float* x  = (const float*)d_in[0];
    const float* dw = (const float*)d_in[1];
    const float* ow = (const float*)d_in[2];
    const float* ob = (const float*)d_in[3];
    const float* w1 = (const float*)d_in[4];
    const float* b1 = (const float*)d_in[5];
    const float* w2 = (const float*)d_in[6];
    const float* b2 = (const float*)d_in[7];
    float* out = (float*)d_out;

    const int branch_smem = 4 * SBUF * (int)sizeof(__nv_bfloat16);  // 73728 B
    cudaFuncSetAttribute(branch_kernel, cudaFuncAttributeMaxDynamicSharedMemorySize, branch_smem);

    transpose_kernel<<<dim3(512, 2, 4), dim3(32, 8)>>>(x);
    dwb_kernel<<<288, 256>>>(dw);
    offset_kernel<<<dim3(64, 4, 4), 256>>>(x, ow, ob);
    branch_kernel<<<dim3(128, 4, 4), 256, branch_smem>>>();
    reduce_kernel<<<1024, 256>>>();
    se_kernel<<<1, 256>>>(w1, b1, w2, b2);
    final_kernel<<<4096, 256>>>(x, out);
}

// round 12
// speedup vs baseline: 1.2366x; 1.0094x over previous
#include <cuda_runtime.h>
#include <cuda_bf16.h>
#include <mma.h>
#include <cstdint>

using namespace nvcuda;

#define HH 128
#define WW 128
#define HWN 16384
#define BHW (4 * 16384)
#define BN 4
#define CN 64

typedef unsigned long long ull;

__device__ __constant__ int c_RATES[4] = {2, 3, 5, 9};

// Scratch (static device globals: allocation-free, graph-capturable)
__device__ float g_xhwc[BN * HWN * CN];             // [b][p][c] f32
__device__ __nv_bfloat16 g_xbf_hi[BN * HWN * CN];   // [b][p][c] bf16 hi
__device__ __nv_bfloat16 g_xbf_lo[BN * HWN * CN];   // [b][p][c] bf16 lo residual
__device__ float g_off[4 * 18 * BHW];               // [j][k2][b*HW+p] planar
__device__ __nv_bfloat16 g_dwb[4 * 9 * 9216];       // [i][k][hi 64x72 | lo 64x72]
__device__ __nv_bfloat16 g_owb[4 * 9 * 4608];       // [j][k][hi 32x72 | lo 32x72]
__device__ float g_cat[4 * BN * CN * HWN];          // [i][b][o][p]
__device__ float g_bsum2[1024];                     // [(i*4+b)*64+o]
__device__ float g_gate[BN * 256];                  // 1 + sigmoid(...)

__device__ __forceinline__ ull pack2(float a, float b) {
    ull r;
    asm("mov.b64 %0, {%1, %2};" : "=l"(r) : "f"(a), "f"(b));
    return r;
}
__device__ __forceinline__ void ffma2(ull& d, ull a, ull b) {
    asm("fma.rn.f32x2 %0, %1, %2, %0;" : "+l"(d) : "l"(a), "l"(b));
}
// split packed f32 pair (fx -> lower half, fy -> upper half) into bf16x2 hi + lo residual
__device__ __forceinline__ void bf16_split(float fx, float fy, unsigned& h, unsigned& l) {
    asm("cvt.rn.bf16x2.f32 %0, %1, %2;" : "=r"(h) : "f"(fy), "f"(fx));
    float hy = __uint_as_float(h & 0xFFFF0000u);
    float hx = __uint_as_float(h << 16);
    float ly = fy - hy, lx = fx - hx;
    asm("cvt.rn.bf16x2.f32 %0, %1, %2;" : "=r"(l) : "f"(ly), "f"(lx));
}

// ---------------- K1: NCHW -> NHWC transpose of x (+ bf16 hi/lo planes) ----------------
__global__ void transpose_kernel(const float* __restrict__ x) {
    __shared__ float tile[32][33];
    int b  = blockIdx.z;
    int p0 = blockIdx.x * 32;
    int c0 = blockIdx.y * 32;
    for (int i = threadIdx.y; i < 32; i += 8)
        tile[i][threadIdx.x] = x[(b * 64 + c0 + i) * HWN + p0 + threadIdx.x];
    __syncthreads();
    for (int i = threadIdx.y; i < 32; i += 8) {
        float v = tile[threadIdx.x][i];
        size_t o = (size_t)(b * HWN + p0 + i) * 64 + c0 + threadIdx.x;
        g_xhwc[o] = v;
        __nv_bfloat16 h = __float2bfloat16(v);
        g_xbf_hi[o] = h;
        g_xbf_lo[o] = __float2bfloat16(v - __bfloat162float(h));
    }
}

// ---------------- K1b: dw -> bf16 hi/lo A tiles [o][c], pitch 72 ----------------
__global__ void dwb_kernel(const float* __restrict__ dw) {
    int idx = blockIdx.x * 256 + threadIdx.x;  // < 73728 = 4*9*64*32
    int i  = idx / 18432;
    int r  = idx % 18432;
    int k  = r / 2048;
    int r2 = r % 2048;
    int o  = r2 >> 5;
    int e  = r2 & 31;
    int c  = e * 2;
    float v0 = dw[((i * 64 + o) * 64 + c) * 9 + k];
    float v1 = dw[((i * 64 + o) * 64 + c + 1) * 9 + k];
    unsigned h, l;
    bf16_split(v0, v1, h, l);
    __nv_bfloat16* base = g_dwb + (size_t)(i * 9 + k) * 9216;
    *(unsigned*)(base + o * 72 + c)        = h;
    *(unsigned*)(base + 4608 + o * 72 + c) = l;
}

// ---------------- K1c: ow -> bf16 hi/lo A tiles [32(pad 18)][64], pitch 72 ----------------
__global__ void owb_kernel(const float* __restrict__ ow) {
    int idx = blockIdx.x * 256 + threadIdx.x;  // < 73728 = 4*9*32*64
    int j  = idx / 18432;
    int r  = idx % 18432;
    int k  = r / 2048;
    int r2 = r % 2048;
    int o  = r2 >> 6;
    int c  = r2 & 63;
    float v = (o < 18) ? ow[((j * 18 + o) * 64 + c) * 9 + k] : 0.f;
    __nv_bfloat16 h = __float2bfloat16(v);
    __nv_bfloat16* base = g_owb + (size_t)(j * 9 + k) * 4608;
    base[o * 72 + c]        = h;
    base[2304 + o * 72 + c] = __float2bfloat16(v - __bfloat162float(h));
}

// ---------------- K2: offset conv via WMMA (bf16 split, regular taps) ----------------
// per (j,b,row): OFF[32(18),128px] = sum_k OW_k[32,64c] @ Xshift_k[64c,128px]; +bias, relu
#define OPIT 72
__global__ __launch_bounds__(256) void offsetw_kernel(const float* __restrict__ ob) {
    __shared__ __nv_bfloat16 SB[2 * 128 * OPIT];  // Bh | Bl (36864 B)
    __nv_bfloat16* Bhs = SB;
    __nv_bfloat16* Bls = SB + 128 * OPIT;

    int row = blockIdx.x, b = blockIdx.y, j = blockIdx.z;
    int p0 = row * 128;
    int rate = c_RATES[j];
    int tid = threadIdx.x;
    int warp = tid >> 5;
    int otile = warp & 1;     // 2 M-tiles (o rows 0-15 / 16-31)
    int pxq = warp >> 1;      // 4 pixel quarters (32 px each)

    wmma::fragment<wmma::accumulator, 16, 16, 16, float> acc[2];
    wmma::fill_fragment(acc[0], 0.f);
    wmma::fill_fragment(acc[1], 0.f);

    int spx = tid >> 1;        // staging pixel
    int part = tid & 1;        // 32-channel half

    for (int k = 0; k < 9; k++) {
        __syncthreads();
        // stage shifted window (boundary -> 0)
        {
            int srow = row + (k / 3 - 1) * rate;
            int sx = spx + (k % 3 - 1) * rate;
            bool v = ((unsigned)srow < HH) && ((unsigned)sx < WW);
            size_t src = ((size_t)b * HWN + srow * WW + sx) * 64 + part * 32;
            uint4* dh = (uint4*)(Bhs + spx * OPIT + part * 32);
            uint4* dl = (uint4*)(Bls + spx * OPIT + part * 32);
            if (v) {
                const uint4* sh = (const uint4*)(g_xbf_hi + src);
                const uint4* sl = (const uint4*)(g_xbf_lo + src);
#pragma unroll
                for (int u = 0; u < 4; u++) { dh[u] = sh[u]; dl[u] = sl[u]; }
            } else {
                uint4 z = make_uint4(0, 0, 0, 0);
#pragma unroll
                for (int u = 0; u < 4; u++) { dh[u] = z; dl[u] = z; }
            }
        }
        __syncthreads();

        const __nv_bfloat16* Ajk = g_owb + (size_t)(j * 9 + k) * 4608;
#pragma unroll
        for (int kc = 0; kc < 4; kc++) {
            wmma::fragment<wmma::matrix_a, 16, 16, 16, __nv_bfloat16, wmma::row_major> Ah, Al;
            wmma::load_matrix_sync(Ah, Ajk + otile * 16 * OPIT + kc * 16, OPIT);
            wmma::load_matrix_sync(Al, Ajk + 2304 + otile * 16 * OPIT + kc * 16, OPIT);
#pragma unroll
            for (int nt = 0; nt < 2; nt++) {
                wmma::fragment<wmma::matrix_b, 16, 16, 16, __nv_bfloat16, wmma::col_major> Bh, Bl;
                int pxb = pxq * 32 + nt * 16;
                wmma::load_matrix_sync(Bh, Bhs + pxb * OPIT + kc * 16, OPIT);
                wmma::load_matrix_sync(Bl, Bls + pxb * OPIT + kc * 16, OPIT);
                wmma::mma_sync(acc[nt], Ah, Bh, acc[nt]);
                wmma::mma_sync(acc[nt], Ah, Bl, acc[nt]);
                wmma::mma_sync(acc[nt], Al, Bh, acc[nt]);
            }
        }
    }

    // epilogue: stage to smem, then bias+relu scatter to planar g_off
    __syncthreads();
    float* osm = (float*)SB;   // 32 x 132 pitch (16896 B)
#pragma unroll
    for (int nt = 0; nt < 2; nt++)
        wmma::store_matrix_sync(osm + (otile * 16) * 132 + pxq * 32 + nt * 16,
                                acc[nt], 132, wmma::mem_row_major);
    __syncthreads();
    for (int idx = tid; idx < 18 * 128; idx += 256) {
        int k2 = idx >> 7, px = idx & 127;
        g_off[(size_t)(j * 18 + k2) * BHW + b * HWN + p0 + px] =
            fmaxf(osm[k2 * 132 + px] + ob[j * 18 + k2], 0.f);
    }
}

// ---------------- K3: gather (bf16 split) + WMMA tensor GEMM per branch ----------------
// tile = 1 image row: OUT[64o,128px] = sum_k DW_k[64o,64c] @ S_k[64c,128px]
// 3-term split: AhBh + AhBl + AlBh.  8 warps = 4 o-tiles x 2 px-halves.
#define SPIT 72
__global__ __launch_bounds__(256) void branch_kernel() {
    __shared__ __nv_bfloat16 Shi[128 * SPIT];
    __shared__ __nv_bfloat16 Slo[128 * SPIT];

    int i = blockIdx.z, b = blockIdx.y, row = blockIdx.x;
    int p0 = row * 128;
    int j = (i + 3) & 3;
    int rate = c_RATES[i];
    int tid = threadIdx.x;
    int warp = tid >> 5;
    int otile = warp & 3, ph = warp >> 2;
    int lane8 = tid & 7;
    int ca = lane8 * 4;

    const float* xb   = &g_xhwc[b * HWN * 64];
    const float* offb = g_off + j * 18 * BHW + b * HWN + p0;

    wmma::fragment<wmma::accumulator, 16, 16, 16, float> acc[4];
#pragma unroll
    for (int nt = 0; nt < 4; nt++) wmma::fill_fragment(acc[nt], 0.f);

    for (int k = 0; k < 9; k++) {
        __syncthreads();
        int kyr = (k / 3 - 1) * rate;
        int kxr = (k % 3 - 1) * rate;
        const float* offY = offb + (2 * k) * BHW;
        const float* offX = offb + (2 * k + 1) * BHW;
#pragma unroll 2
        for (int pass = 0; pass < 4; pass++) {
            int sp = pass * 32 + (tid >> 3);
            float dy = __ldg(offY + sp);
            float dx = __ldg(offX + sp);
            float py = (float)(row + kyr) + dy;
            float px = (float)(sp + kxr) + dx;
            float fy = floorf(py), fx = floorf(px);
            int iy0 = (int)fy, ix0 = (int)fx;
            float wy1 = py - fy, wx1 = px - fx;
            float wy0 = 1.f - wy1, wx0 = 1.f - wx1;
            bool vy0 = (unsigned)iy0 < HH, vy1 = (unsigned)(iy0 + 1) < HH;
            bool vx0 = (unsigned)ix0 < WW, vx1 = (unsigned)(ix0 + 1) < WW;
            float w00 = (vy0 && vx0) ? wy0 * wx0 : 0.f;
            float w01 = (vy0 && vx1) ? wy0 * wx1 : 0.f;
            float w10 = (vy1 && vx0) ? wy1 * wx0 : 0.f;
            float w11 = (vy1 && vx1) ? wy1 * wx1 : 0.f;
            ull w00d = pack2(w00, w00), w01d = pack2(w01, w01);
            ull w10d = pack2(w10, w10), w11d = pack2(w11, w11);
            int cy0 = min(max(iy0, 0), HH - 1), cy1 = min(max(iy0 + 1, 0), HH - 1);
            int cx0 = min(max(ix0, 0), WW - 1), cx1 = min(max(ix0 + 1, 0), WW - 1);
            const float* b00 = xb + (cy0 * WW + cx0) * 64;
            const float* b01 = xb + (cy0 * WW + cx1) * 64;
            const float* b10 = xb + (cy1 * WW + cx0) * 64;
            const float* b11 = xb + (cy1 * WW + cx1) * 64;
#pragma unroll
            for (int half = 0; half < 2; half++) {
                int cc = ca + half * 32;
                ulonglong2 t00 = *(const ulonglong2*)(b00 + cc);
                ulonglong2 t01 = *(const ulonglong2*)(b01 + cc);
                ulonglong2 t10 = *(const ulonglong2*)(b10 + cc);
                ulonglong2 t11 = *(const ulonglong2*)(b11 + cc);
                ull r0 = 0, r1 = 0;
                ffma2(r0, w00d, t00.x); ffma2(r1, w00d, t00.y);
                ffma2(r0, w01d, t01.x); ffma2(r1, w01d, t01.y);
                ffma2(r0, w10d, t10.x); ffma2(r1, w10d, t10.y);
                ffma2(r0, w11d, t11.x); ffma2(r1, w11d, t11.y);
                float2 f0 = *(float2*)&r0, f1 = *(float2*)&r1;
                unsigned h0, l0, h1, l1;
                bf16_split(f0.x, f0.y, h0, l0);
                bf16_split(f1.x, f1.y, h1, l1);
                unsigned* dh = (unsigned*)(Shi + sp * SPIT + cc);
                dh[0] = h0; dh[1] = h1;
                unsigned* dl = (unsigned*)(Slo + sp * SPIT + cc);
                dl[0] = l0; dl[1] = l1;
            }
        }
        __syncthreads();

        const __nv_bfloat16* Ahg = g_dwb + (size_t)(i * 9 + k) * 9216;
        const __nv_bfloat16* Alg = Ahg + 4608;
#pragma unroll
        for (int kc = 0; kc < 4; kc++) {
            wmma::fragment<wmma::matrix_a, 16, 16, 16, __nv_bfloat16, wmma::row_major> Ah, Al;
            wmma::load_matrix_sync(Ah, Ahg + otile * 16 * SPIT + kc * 16, SPIT);
            wmma::load_matrix_sync(Al, Alg + otile * 16 * SPIT + kc * 16, SPIT);
#pragma unroll
            for (int nt = 0; nt < 4; nt++) {
                wmma::fragment<wmma::matrix_b, 16, 16, 16, __nv_bfloat16, wmma::col_major> Bh, Bl;
                int pxb = ph * 64 + nt * 16;
                wmma::load_matrix_sync(Bh, Shi + pxb * SPIT + kc * 16, SPIT);
                wmma::load_matrix_sync(Bl, Slo + pxb * SPIT + kc * 16, SPIT);
                wmma::mma_sync(acc[nt], Ah, Bh, acc[nt]);
                wmma::mma_sync(acc[nt], Ah, Bl, acc[nt]);
                wmma::mma_sync(acc[nt], Al, Bh, acc[nt]);
            }
        }
    }

    float* outp = &g_cat[((i * 4 + b) * 64) * HWN];
#pragma unroll
    for (int nt = 0; nt < 4; nt++)
        wmma::store_matrix_sync(outp + (otile * 16) * HWN + p0 + ph * 64 + nt * 16,
                                acc[nt], HWN, wmma::mem_row_major);
}

// ---------------- K3b: per-(i,b,o) channel sums for SE ----------------
__global__ void reduce_kernel() {
    __shared__ float sred[256];
    int idx = blockIdx.x;  // 0..1023
    const float4* src = (const float4*)(g_cat + (size_t)idx * HWN);
    float s = 0.f;
    for (int t = threadIdx.x; t < 4096; t += 256) {
        float4 v = src[t];
        s += v.x + v.y + v.z + v.w;
    }
    sred[threadIdx.x] = s;
    __syncthreads();
    for (int st = 128; st > 0; st >>= 1) {
        if (threadIdx.x < st) sred[threadIdx.x] += sred[threadIdx.x + st];
        __syncthreads();
    }
    if (threadIdx.x == 0) g_bsum2[idx] = sred[0];
}

// ---------------- K4: SE MLP (tiny, one block) ----------------
__global__ void se_kernel(const float* __restrict__ w1, const float* __restrict__ b1,
                          const float* __restrict__ w2, const float* __restrict__ b2) {
    __shared__ float gm[4 * 256];
    __shared__ float h1[4 * 64];
    int tid = threadIdx.x;  // 256
    for (int idx = tid; idx < 1024; idx += 256) {
        int b = idx >> 8, ch = idx & 255;
        gm[b * 256 + ch] = g_bsum2[((ch >> 6) * 4 + b) * 64 + (ch & 63)] * (1.f / 16384.f);
    }
    __syncthreads();
    {
        int b = tid >> 6, oc = tid & 63;
        float a = b1[oc];
        for (int ch = 0; ch < 256; ch++) a += w1[oc * 256 + ch] * gm[b * 256 + ch];
        h1[b * 64 + oc] = fmaxf(a, 0.f);
    }
    __syncthreads();
    for (int idx = tid; idx < 1024; idx += 256) {
        int b = idx >> 8, ch = idx & 255;
        float a = b2[ch];
        for (int oc = 0; oc < 64; oc++) a += w2[ch * 64 + oc] * h1[b * 64 + oc];
        g_gate[b * 256 + ch] = 1.f + 1.f / (1.f + expf(-a));
    }
}

// ---------------- K5: gated fuse + residual ----------------
__global__ void final_kernel(const float* __restrict__ x, float* __restrict__ out) {
    int idx = blockIdx.x * 256 + threadIdx.x;  // < 1048576 float4s
    int p4 = idx & 4095;
    int o  = (idx >> 12) & 63;
    int b  = idx >> 18;
    float4 a = ((const float4*)x)[idx];
#pragma unroll
    for (int i = 0; i < 4; i++) {
        float g = g_gate[b * 256 + i * 64 + o];
        float4 cv = ((const float4*)g_cat)[((i * 4 + b) * 64 + o) * 4096 + p4];
        a.x += g * cv.x;
        a.y += g * cv.y;
        a.z += g * cv.z;
        a.w += g * cv.w;
    }
    ((float4*)out)[idx] = a;
}

extern "C" void kernel_launch(void* const* d_in, const int* in_sizes, int n_in,
                              void* d_out, int out_size) {
    const float* x  = (const float*)d_in[0];
    const float* dw = (const float*)d_in[1];
    const float* ow = (const float*)d_in[2];
    const float* ob = (const float*)d_in[3];
    const float* w1 = (const float*)d_in[4];
    const float* b1 = (const float*)d_in[5];
    const float* w2 = (const float*)d_in[6];
    const float* b2 = (const float*)d_in[7];
    float* out = (float*)d_out;

    transpose_kernel<<<dim3(512, 2, 4), dim3(32, 8)>>>(x);
    dwb_kernel<<<288, 256>>>(dw);
    owb_kernel<<<288, 256>>>(ow);
    offsetw_kernel<<<dim3(128, 4, 4), 256>>>(ob);
    branch_kernel<<<dim3(128, 4, 4), 256>>>();
    reduce_kernel<<<1024, 256>>>();
    se_kernel<<<1, 256>>>(w1, b1, w2, b2);
    final_kernel<<<4096, 256>>>(x, out);
}

// round 13
// speedup vs baseline: 1.3425x; 1.0856x over previous
#include <cuda_runtime.h>
#include <cuda_bf16.h>
#include <mma.h>
#include <cstdint>

using namespace nvcuda;

#define HH 128
#define WW 128
#define HWN 16384
#define BHW (4 * 16384)
#define BN 4
#define CN 64

typedef unsigned long long ull;

__device__ __constant__ int c_RATES[4] = {2, 3, 5, 9};

// Scratch (static device globals: allocation-free, graph-capturable)
__device__ float g_xhwc[BN * HWN * CN];             // [b][p][c] f32
__device__ __nv_bfloat16 g_xbf_hi[BN * HWN * CN];   // [b][p][c] bf16 hi
__device__ __nv_bfloat16 g_xbf_lo[BN * HWN * CN];   // [b][p][c] bf16 lo residual
__device__ float g_off[4 * 18 * BHW];               // [j][k2][b*HW+p] planar
__device__ __nv_bfloat16 g_dwb[4 * 9 * 9216];       // [i][k][hi 64x72 | lo 64x72]
__device__ __nv_bfloat16 g_owb[4 * 9 * 4608];       // [j][k][hi 32x72 | lo 32x72]
__device__ float g_cat[4 * BN * CN * HWN];          // [i][b][o][p]
__device__ float g_bsum2[1024];                     // [(i*4+b)*64+o]
__device__ float g_gate[BN * 256];                  // 1 + sigmoid(...)

__device__ __forceinline__ ull pack2(float a, float b) {
    ull r;
    asm("mov.b64 %0, {%1, %2};" : "=l"(r) : "f"(a), "f"(b));
    return r;
}
__device__ __forceinline__ void ffma2(ull& d, ull a, ull b) {
    asm("fma.rn.f32x2 %0, %1, %2, %0;" : "+l"(d) : "l"(a), "l"(b));
}
// split packed f32 pair (fx -> lower half, fy -> upper half) into bf16x2 hi + lo residual
__device__ __forceinline__ void bf16_split(float fx, float fy, unsigned& h, unsigned& l) {
    asm("cvt.rn.bf16x2.f32 %0, %1, %2;" : "=r"(h) : "f"(fy), "f"(fx));
    float hy = __uint_as_float(h & 0xFFFF0000u);
    float hx = __uint_as_float(h << 16);
    float ly = fy - hy, lx = fx - hx;
    asm("cvt.rn.bf16x2.f32 %0, %1, %2;" : "=r"(l) : "f"(ly), "f"(lx));
}

// ---------------- K1: NCHW -> NHWC transpose of x (+ bf16 hi/lo planes) ----------------
__global__ void transpose_kernel(const float* __restrict__ x) {
    __shared__ float tile[32][33];
    int b  = blockIdx.z;
    int p0 = blockIdx.x * 32;
    int c0 = blockIdx.y * 32;
    for (int i = threadIdx.y; i < 32; i += 8)
        tile[i][threadIdx.x] = x[(b * 64 + c0 + i) * HWN + p0 + threadIdx.x];
    __syncthreads();
    for (int i = threadIdx.y; i < 32; i += 8) {
        float v = tile[threadIdx.x][i];
        size_t o = (size_t)(b * HWN + p0 + i) * 64 + c0 + threadIdx.x;
        g_xhwc[o] = v;
        __nv_bfloat16 h = __float2bfloat16(v);
        g_xbf_hi[o] = h;
        g_xbf_lo[o] = __float2bfloat16(v - __bfloat162float(h));
    }
}

// ---------------- K1b: dw -> bf16 hi/lo A tiles [o][c], pitch 72 ----------------
__global__ void dwb_kernel(const float* __restrict__ dw) {
    int idx = blockIdx.x * 256 + threadIdx.x;  // < 73728 = 4*9*64*32
    int i  = idx / 18432;
    int r  = idx % 18432;
    int k  = r / 2048;
    int r2 = r % 2048;
    int o  = r2 >> 5;
    int e  = r2 & 31;
    int c  = e * 2;
    float v0 = dw[((i * 64 + o) * 64 + c) * 9 + k];
    float v1 = dw[((i * 64 + o) * 64 + c + 1) * 9 + k];
    unsigned h, l;
    bf16_split(v0, v1, h, l);
    __nv_bfloat16* base = g_dwb + (size_t)(i * 9 + k) * 9216;
    *(unsigned*)(base + o * 72 + c)        = h;
    *(unsigned*)(base + 4608 + o * 72 + c) = l;
}

// ---------------- K1c: ow -> bf16 hi/lo A tiles [32(pad 18)][64], pitch 72 ----------------
__global__ void owb_kernel(const float* __restrict__ ow) {
    int idx = blockIdx.x * 256 + threadIdx.x;  // < 73728 = 4*9*32*64
    int j  = idx / 18432;
    int r  = idx % 18432;
    int k  = r / 2048;
    int r2 = r % 2048;
    int o  = r2 >> 6;
    int c  = r2 & 63;
    float v = (o < 18) ? ow[((j * 18 + o) * 64 + c) * 9 + k] : 0.f;
    __nv_bfloat16 h = __float2bfloat16(v);
    __nv_bfloat16* base = g_owb + (size_t)(j * 9 + k) * 4608;
    base[o * 72 + c]        = h;
    base[2304 + o * 72 + c] = __float2bfloat16(v - __bfloat162float(h));
}

// ---------------- K2: offset conv via WMMA (bf16 split, regular taps) ----------------
// per (j,b,row): OFF[32(18),128px] = sum_k OW_k[32,64c] @ Xshift_k[64c,128px]; +bias, relu
// staging: 8 lanes per pixel x 16B chunks -> full-line LDG.128 (R6 lesson)
#define OPIT 72
__global__ __launch_bounds__(256) void offsetw_kernel(const float* __restrict__ ob) {
    __shared__ __nv_bfloat16 SB[2 * 128 * OPIT];  // Bh | Bl (36864 B)
    __nv_bfloat16* Bhs = SB;
    __nv_bfloat16* Bls = SB + 128 * OPIT;

    int row = blockIdx.x, b = blockIdx.y, j = blockIdx.z;
    int p0 = row * 128;
    int rate = c_RATES[j];
    int tid = threadIdx.x;
    int warp = tid >> 5;
    int otile = warp & 1;     // 2 M-tiles (o rows 0-15 / 16-31)
    int pxq = warp >> 1;      // 4 pixel quarters (32 px each)

    wmma::fragment<wmma::accumulator, 16, 16, 16, float> acc[2];
    wmma::fill_fragment(acc[0], 0.f);
    wmma::fill_fragment(acc[1], 0.f);

    int lane8 = tid & 7;      // 16B channel chunk (8 bf16)
    int cbase = lane8 * 8;

    for (int k = 0; k < 9; k++) {
        __syncthreads();
        // stage shifted window: 4 passes x 32 px; 8 lanes cover one pixel's 128B line
        {
            int srow = row + (k / 3 - 1) * rate;
            int xsh = (k % 3 - 1) * rate;
            bool vr = (unsigned)srow < HH;
#pragma unroll
            for (int pass = 0; pass < 4; pass++) {
                int px = pass * 32 + (tid >> 3);
                int sx = px + xsh;
                bool v = vr && ((unsigned)sx < WW);
                uint4 vh = make_uint4(0, 0, 0, 0), vl = make_uint4(0, 0, 0, 0);
                if (v) {
                    size_t src = ((size_t)b * HWN + srow * WW + sx) * 64 + cbase;
                    vh = *(const uint4*)(g_xbf_hi + src);
                    vl = *(const uint4*)(g_xbf_lo + src);
                }
                *(uint4*)(Bhs + px * OPIT + cbase) = vh;
                *(uint4*)(Bls + px * OPIT + cbase) = vl;
            }
        }
        __syncthreads();

        const __nv_bfloat16* Ajk = g_owb + (size_t)(j * 9 + k) * 4608;
#pragma unroll
        for (int kc = 0; kc < 4; kc++) {
            wmma::fragment<wmma::matrix_a, 16, 16, 16, __nv_bfloat16, wmma::row_major> Ah, Al;
            wmma::load_matrix_sync(Ah, Ajk + otile * 16 * OPIT + kc * 16, OPIT);
            wmma::load_matrix_sync(Al, Ajk + 2304 + otile * 16 * OPIT + kc * 16, OPIT);
#pragma unroll
            for (int nt = 0; nt < 2; nt++) {
                wmma::fragment<wmma::matrix_b, 16, 16, 16, __nv_bfloat16, wmma::col_major> Bh, Bl;
                int pxb = pxq * 32 + nt * 16;
                wmma::load_matrix_sync(Bh, Bhs + pxb * OPIT + kc * 16, OPIT);
                wmma::load_matrix_sync(Bl, Bls + pxb * OPIT + kc * 16, OPIT);
                wmma::mma_sync(acc[nt], Ah, Bh, acc[nt]);
                wmma::mma_sync(acc[nt], Ah, Bl, acc[nt]);
                wmma::mma_sync(acc[nt], Al, Bh, acc[nt]);
            }
        }
    }

    // epilogue: stage to smem, then bias+relu scatter to planar g_off
    __syncthreads();
    float* osm = (float*)SB;   // 32 x 132 pitch (16896 B)
#pragma unroll
    for (int nt = 0; nt < 2; nt++)
        wmma::store_matrix_sync(osm + (otile * 16) * 132 + pxq * 32 + nt * 16,
                                acc[nt], 132, wmma::mem_row_major);
    __syncthreads();
    for (int idx = tid; idx < 18 * 128; idx += 256) {
        int k2 = idx >> 7, px = idx & 127;
        g_off[(size_t)(j * 18 + k2) * BHW + b * HWN + p0 + px] =
            fmaxf(osm[k2 * 132 + px] + ob[j * 18 + k2], 0.f);
    }
}

// ---------------- K3: gather (bf16 split) + WMMA tensor GEMM per branch ----------------
// tile = 1 image row: OUT[64o,128px] = sum_k DW_k[64o,64c] @ S_k[64c,128px]
// 3-term split: AhBh + AhBl + AlBh.  8 warps = 4 o-tiles x 2 px-halves.
#define SPIT 72
__global__ __launch_bounds__(256) void branch_kernel() {
    __shared__ __nv_bfloat16 Shi[128 * SPIT];
    __shared__ __nv_bfloat16 Slo[128 * SPIT];

    int i = blockIdx.z, b = blockIdx.y, row = blockIdx.x;
    int p0 = row * 128;
    int j = (i + 3) & 3;
    int rate = c_RATES[i];
    int tid = threadIdx.x;
    int warp = tid >> 5;
    int otile = warp & 3, ph = warp >> 2;
    int lane8 = tid & 7;
    int ca = lane8 * 4;

    const float* xb   = &g_xhwc[b * HWN * 64];
    const float* offb = g_off + j * 18 * BHW + b * HWN + p0;

    wmma::fragment<wmma::accumulator, 16, 16, 16, float> acc[4];
#pragma unroll
    for (int nt = 0; nt < 4; nt++) wmma::fill_fragment(acc[nt], 0.f);

    for (int k = 0; k < 9; k++) {
        __syncthreads();
        int kyr = (k / 3 - 1) * rate;
        int kxr = (k % 3 - 1) * rate;
        const float* offY = offb + (2 * k) * BHW;
        const float* offX = offb + (2 * k + 1) * BHW;
#pragma unroll 2
        for (int pass = 0; pass < 4; pass++) {
            int sp = pass * 32 + (tid >> 3);
            float dy = __ldg(offY + sp);
            float dx = __ldg(offX + sp);
            float py = (float)(row + kyr) + dy;
            float px = (float)(sp + kxr) + dx;
            float fy = floorf(py), fx = floorf(px);
            int iy0 = (int)fy, ix0 = (int)fx;
            float wy1 = py - fy, wx1 = px - fx;
            float wy0 = 1.f - wy1, wx0 = 1.f - wx1;
            bool vy0 = (unsigned)iy0 < HH, vy1 = (unsigned)(iy0 + 1) < HH;
            bool vx0 = (unsigned)ix0 < WW, vx1 = (unsigned)(ix0 + 1) < WW;
            float w00 = (vy0 && vx0) ? wy0 * wx0 : 0.f;
            float w01 = (vy0 && vx1) ? wy0 * wx1 : 0.f;
            float w10 = (vy1 && vx0) ? wy1 * wx0 : 0.f;
            float w11 = (vy1 && vx1) ? wy1 * wx1 : 0.f;
            ull w00d = pack2(w00, w00), w01d = pack2(w01, w01);
            ull w10d = pack2(w10, w10), w11d = pack2(w11, w11);
            int cy0 = min(max(iy0, 0), HH - 1), cy1 = min(max(iy0 + 1, 0), HH - 1);
            int cx0 = min(max(ix0, 0), WW - 1), cx1 = min(max(ix0 + 1, 0), WW - 1);
            const float* b00 = xb + (cy0 * WW + cx0) * 64;
            const float* b01 = xb + (cy0 * WW + cx1) * 64;
            const float* b10 = xb + (cy1 * WW + cx0) * 64;
            const float* b11 = xb + (cy1 * WW + cx1) * 64;
#pragma unroll
            for (int half = 0; half < 2; half++) {
                int cc = ca + half * 32;
                ulonglong2 t00 = *(const ulonglong2*)(b00 + cc);
                ulonglong2 t01 = *(const ulonglong2*)(b01 + cc);
                ulonglong2 t10 = *(const ulonglong2*)(b10 + cc);
                ulonglong2 t11 = *(const ulonglong2*)(b11 + cc);
                ull r0 = 0, r1 = 0;
                ffma2(r0, w00d, t00.x); ffma2(r1, w00d, t00.y);
                ffma2(r0, w01d, t01.x); ffma2(r1, w01d, t01.y);
                ffma2(r0, w10d, t10.x); ffma2(r1, w10d, t10.y);
                ffma2(r0, w11d, t11.x); ffma2(r1, w11d, t11.y);
                float2 f0 = *(float2*)&r0, f1 = *(float2*)&r1;
                unsigned h0, l0, h1, l1;
                bf16_split(f0.x, f0.y, h0, l0);
                bf16_split(f1.x, f1.y, h1, l1);
                unsigned* dh = (unsigned*)(Shi + sp * SPIT + cc);
                dh[0] = h0; dh[1] = h1;
                unsigned* dl = (unsigned*)(Slo + sp * SPIT + cc);
                dl[0] = l0; dl[1] = l1;
            }
        }
        __syncthreads();

        const __nv_bfloat16* Ahg = g_dwb + (size_t)(i * 9 + k) * 9216;
        const __nv_bfloat16* Alg = Ahg + 4608;
#pragma unroll
        for (int kc = 0; kc < 4; kc++) {
            wmma::fragment<wmma::matrix_a, 16, 16, 16, __nv_bfloat16, wmma::row_major> Ah, Al;
            wmma::load_matrix_sync(Ah, Ahg + otile * 16 * SPIT + kc * 16, SPIT);
            wmma::load_matrix_sync(Al, Alg + otile * 16 * SPIT + kc * 16, SPIT);
#pragma unroll
            for (int nt = 0; nt < 4; nt++) {
                wmma::fragment<wmma::matrix_b, 16, 16, 16, __nv_bfloat16, wmma::col_major> Bh, Bl;
                int pxb = ph * 64 + nt * 16;
                wmma::load_matrix_sync(Bh, Shi + pxb * SPIT + kc * 16, SPIT);
                wmma::load_matrix_sync(Bl, Slo + pxb * SPIT + kc * 16, SPIT);
                wmma::mma_sync(acc[nt], Ah, Bh, acc[nt]);
                wmma::mma_sync(acc[nt], Ah, Bl, acc[nt]);
                wmma::mma_sync(acc[nt], Al, Bh, acc[nt]);
            }
        }
    }

    float* outp = &g_cat[((i * 4 + b) * 64) * HWN];
#pragma unroll
    for (int nt = 0; nt < 4; nt++)
        wmma::store_matrix_sync(outp + (otile * 16) * HWN + p0 + ph * 64 + nt * 16,
                                acc[nt], HWN, wmma::mem_row_major);
}

// ---------------- K3b: per-(i,b,o) channel sums for SE ----------------
__global__ void reduce_kernel() {
    __shared__ float sred[256];
    int idx = blockIdx.x;  // 0..1023
    const float4* src = (const float4*)(g_cat + (size_t)idx * HWN);
    float s = 0.f;
    for (int t = threadIdx.x; t < 4096; t += 256) {
        float4 v = src[t];
        s += v.x + v.y + v.z + v.w;
    }
    sred[threadIdx.x] = s;
    __syncthreads();
    for (int st = 128; st > 0; st >>= 1) {
        if (threadIdx.x < st) sred[threadIdx.x] += sred[threadIdx.x + st];
        __syncthreads();
    }
    if (threadIdx.x == 0) g_bsum2[idx] = sred[0];
}

// ---------------- K4: SE MLP (tiny, one block) ----------------
__global__ void se_kernel(const float* __restrict__ w1, const float* __restrict__ b1,
                          const float* __restrict__ w2, const float* __restrict__ b2) {
    __shared__ float gm[4 * 256];
    __shared__ float h1[4 * 64];
    int tid = threadIdx.x;  // 256
    for (int idx = tid; idx < 1024; idx += 256) {
        int b = idx >> 8, ch = idx & 255;
        gm[b * 256 + ch] = g_bsum2[((ch >> 6) * 4 + b) * 64 + (ch & 63)] * (1.f / 16384.f);
    }
    __syncthreads();
    {
        int b = tid >> 6, oc = tid & 63;
        float a = b1[oc];
        for (int ch = 0; ch < 256; ch++) a += w1[oc * 256 + ch] * gm[b * 256 + ch];
        h1[b * 64 + oc] = fmaxf(a, 0.f);
    }
    __syncthreads();
    for (int idx = tid; idx < 1024; idx += 256) {
        int b = idx >> 8, ch = idx & 255;
        float a = b2[ch];
        for (int oc = 0; oc < 64; oc++) a += w2[ch * 64 + oc] * h1[b * 64 + oc];
        g_gate[b * 256 + ch] = 1.f + 1.f / (1.f + expf(-a));
    }
}

// ---------------- K5: gated fuse + residual ----------------
__global__ void final_kernel(const float* __restrict__ x, float* __restrict__ out) {
    int idx = blockIdx.x * 256 + threadIdx.x;  // < 1048576 float4s
    int p4 = idx & 4095;
    int o  = (idx >> 12) & 63;
    int b  = idx >> 18;
    float4 a = ((const float4*)x)[idx];
#pragma unroll
    for (int i = 0; i < 4; i++) {
        float g = g_gate[b * 256 + i * 64 + o];
        float4 cv = ((const float4*)g_cat)[((i * 4 + b) * 64 + o) * 4096 + p4];
        a.x += g * cv.x;
        a.y += g * cv.y;
        a.z += g * cv.z;
        a.w += g * cv.w;
    }
    ((float4*)out)[idx] = a;
}

extern "C" void kernel_launch(void* const* d_in, const int* in_sizes, int n_in,
                              void* d_out, int out_size) {
    const float* x  = (const float*)d_in[0];
    const float* dw = (const float*)d_in[1];
    const float* ow = (const float*)d_in[2];
    const float* ob = (const float*)d_in[3];
    const float* w1 = (const float*)d_in[4];
    const float* b1 = (const float*)d_in[5];
    const float* w2 = (const float*)d_in[6];
    const float* b2 = (const float*)d_in[7];
    float* out = (float*)d_out;

    transpose_kernel<<<dim3(512, 2, 4), dim3(32, 8)>>>(x);
    dwb_kernel<<<288, 256>>>(dw);
    owb_kernel<<<288, 256>>>(ow);
    offsetw_kernel<<<dim3(128, 4, 4), 256>>>(ob);
    branch_kernel<<<dim3(128, 4, 4), 256>>>();
    reduce_kernel<<<1024, 256>>>();
    se_kernel<<<1, 256>>>(w1, b1, w2, b2);
    final_kernel<<<4096, 256>>>(x, out);
}